// round 1
// baseline (speedup 1.0000x reference)
#include <cuda_runtime.h>
#include <math.h>

#define Bb 8
#define IN_N 8
#define OUT_N 8
#define SEQ 256
#define FEAT 64
#define NCg 99
#define KSZ 15

// ---------------- scratch (static device globals; no allocs) ----------------
__device__ float g_mu[Bb*IN_N*FEAT];
__device__ float g_rinv[Bb*IN_N*FEAT];
__device__ float g_act[Bb*IN_N*OUT_N*SEQ*FEAT];     // 32 MB
__device__ float g_energy[Bb*IN_N*OUT_N];
__device__ float g_mask[Bb*IN_N*OUT_N];
__device__ float g_mult[Bb*IN_N*OUT_N];
__device__ float g_comb[Bb*OUT_N*SEQ*FEAT];          // 4 MB
__device__ float g_K [OUT_N*Bb*SEQ*256];             // 16 MB  K_ln[jb][s][d]
__device__ float g_QT[OUT_N*Bb*256*SEQ];             // 16 MB  Q_ln^T[jb][d][t]
__device__ float g_raw[OUT_N*Bb*SEQ*SEQ];            // 16 MB  raw / attn

#define OFF_PROJ (Bb*OUT_N*SEQ*FEAT)                 // 1048576

// ---------------- helpers ----------------
__device__ __forceinline__ float blk_sum(float v, float* red, int n) {
    int t = threadIdx.x;
    red[t] = v; __syncthreads();
    for (int st = n >> 1; st; st >>= 1) {
        if (t < st) red[t] += red[t + st];
        __syncthreads();
    }
    float r = red[0]; __syncthreads();
    return r;
}

// ---------------- K1: per-(b,i,f) mean/var over seq ----------------
__global__ void k_stats(const float* __restrict__ x) {
    int bi = blockIdx.x;          // b*8+i
    int f  = threadIdx.x;         // 64
    const float* p = x + (size_t)bi * SEQ * FEAT + f;
    float s = 0.f, s2 = 0.f;
    for (int t = 0; t < SEQ; t++) { float v = p[t * FEAT]; s += v; s2 += v * v; }
    float mu  = s * (1.f / SEQ);
    float var = s2 * (1.f / SEQ) - mu * mu;
    g_mu[bi * FEAT + f]   = mu;
    g_rinv[bi * FEAT + f] = rsqrtf(var + 1e-5f);
}

// ---------------- K2: activated + energy (per (b,i)) ----------------
__global__ void k_act(const float* __restrict__ x, const float* __restrict__ grid,
                      const float* __restrict__ sw, const float* __restrict__ omiga) {
    int bi = blockIdx.x;          // 64 blocks
    int tid = threadIdx.x;        // 256
    __shared__ float s_grid[NCg];
    __shared__ float s_sw[OUT_N][NCg];
    __shared__ float s_om[OUT_N];
    __shared__ float red[256];
    int i = bi & 7;
    for (int c = tid; c < NCg; c += 256) s_grid[c] = grid[c];
    for (int oc = tid; oc < OUT_N * NCg; oc += 256)
        s_sw[oc / NCg][oc % NCg] = sw[i * OUT_N * NCg + oc];
    if (tid < OUT_N) s_om[tid] = fabsf(omiga[i * OUT_N + tid]);
    __syncthreads();

    float eacc[OUT_N];
    #pragma unroll
    for (int o = 0; o < OUT_N; o++) eacc[o] = 0.f;

    const float* xb = x + (size_t)bi * SEQ * FEAT;
    float* ab = g_act + (size_t)bi * OUT_N * SEQ * FEAT;

    for (int e = tid; e < SEQ * FEAT; e += 256) {
        int f = e & 63;
        float xv = xb[e];
        float xn = (xv - g_mu[bi * FEAT + f]) * g_rinv[bi * FEAT + f] * 0.5f;
        xn = fminf(fmaxf(xn, -0.99f), 0.99f);
        float u = (xn + 1.f) * 49.f;       // h = 2/98
        int m = (int)floorf(u);
        float bv[4]; int ci[4];
        #pragma unroll
        for (int k = 0; k < 4; k++) {
            int c = m - 1 + k;
            float val = 0.f;
            if (c >= 0 && c < NCg) {
                float d  = fabsf(xn - s_grid[c]) * 49.f;
                float r2 = fmaxf(2.f - d, 0.f);
                float r1 = fmaxf(1.f - d, 0.f);
                val = r2 * r2 * r2 * (1.f / 6.f) - r1 * r1 * r1 * (4.f / 6.f);
            }
            ci[k] = min(max(c, 0), NCg - 1);
            bv[k] = val;
        }
        #pragma unroll
        for (int o = 0; o < OUT_N; o++) {
            float a = s_om[o] * xv;
            #pragma unroll
            for (int k = 0; k < 4; k++) a = fmaf(bv[k], s_sw[o][ci[k]], a);
            ab[(size_t)o * SEQ * FEAT + e] = a;
            eacc[o] = fmaf(a, a, eacc[o]);
        }
    }
    for (int o = 0; o < OUT_N; o++) {
        float tot = blk_sum(eacc[o], red, 256);
        if (tid == 0) g_energy[bi * OUT_N + o] = tot;
        __syncthreads();
    }
}

// ---------------- K3: mask / mult ----------------
__global__ void k_maskmult(const float* __restrict__ tau, const float* __restrict__ temp) {
    int idx = threadIdx.x;        // 512
    int o = idx & 7, i = (idx >> 3) & 7;
    float en = g_energy[idx] * (1.f / (SEQ * FEAT));
    float es = sqrtf(en + 1e-8f);
    float ta = fabsf(tau[i * OUT_N + o]);
    float tv = fabsf(temp[0]) + 1e-4f;   // sqrt(256/256)=1
    g_mask[idx] = 1.f / (1.f + expf(-(es - ta) / tv));
    g_mult[idx] = es / (ta + 1e-8f);
}

// ---------------- K4: combined + LN + x_prime (projs) ----------------
__global__ void k_comb(float* __restrict__ out,
                       const float* __restrict__ ln_w, const float* __restrict__ ln_b,
                       const float* __restrict__ W2s, const float* __restrict__ bs) {
    int blk = blockIdx.x;         // bj*256 + s   (bj = b*8+j)
    int s = blk & 255, bj = blk >> 8;
    int b = bj >> 3, j = bj & 7;
    int f = threadIdx.x;          // 64
    __shared__ float red[64];
    __shared__ float xnsh[64];

    float c = 0.f;
    #pragma unroll
    for (int i = 0; i < IN_N; i++) {
        c = fmaf(g_act[((((size_t)(b * 8 + i)) * OUT_N + j) * SEQ + s) * FEAT + f],
                 g_mask[(b * 8 + i) * OUT_N + j], c);
    }
    g_comb[((size_t)bj * SEQ + s) * FEAT + f] = c;

    float tot  = blk_sum(c, red, 64);
    float tot2 = blk_sum(c * c, red, 64);
    float mean = tot * (1.f / 64.f);
    float var  = tot2 * (1.f / 64.f) - mean * mean;
    float xn = (c - mean) * rsqrtf(var + 1e-5f) * ln_w[j * FEAT + f] + ln_b[j * FEAT + f];
    xnsh[f] = xn; __syncthreads();

    float xp = bs[((size_t)j * SEQ + s) * FEAT + f];
    const float* W2 = W2s + (size_t)j * FEAT * FEAT;
    #pragma unroll 8
    for (int k = 0; k < FEAT; k++) xp = fmaf(xnsh[k], W2[k * FEAT + f], xp);
    out[OFF_PROJ + ((size_t)bj * SEQ + s) * FEAT + f] = xp;
}

// ---------------- K5: K/Q layernorm ----------------
__global__ void k_kq(const float* __restrict__ proj) {
    int blk = blockIdx.x;         // jb*256 + s  (jb = j*8+b)
    int s = blk & 255, jb = blk >> 8;
    int j = jb >> 3, b = jb & 7;
    int d = threadIdx.x;          // 256
    int g = d >> 6, f = d & 63;
    __shared__ float red[256];

    int iK = 2 * g, iQ = 2 * g + 1;
    int mK = (b * 8 + iK) * OUT_N + j, mQ = (b * 8 + iQ) * OUT_N + j;
    float kv = proj[(((size_t)(b * 8 + iK)) * SEQ + s) * FEAT + f] * g_mult[mK] * g_mask[mK];
    float qv = proj[(((size_t)(b * 8 + iQ)) * SEQ + s) * FEAT + f] * g_mult[mQ] * g_mask[mQ];

    float ks  = blk_sum(kv, red, 256);
    float ks2 = blk_sum(kv * kv, red, 256);
    float qs  = blk_sum(qv, red, 256);
    float qs2 = blk_sum(qv * qv, red, 256);
    float km = ks * (1.f / 256.f), kvar = ks2 * (1.f / 256.f) - km * km;
    float qm = qs * (1.f / 256.f), qvar = qs2 * (1.f / 256.f) - qm * qm;
    float kn = (kv - km) * rsqrtf(kvar + 1e-5f);
    float qn = (qv - qm) * rsqrtf(qvar + 1e-5f);
    g_K [((size_t)jb * SEQ + s) * 256 + d] = kn;
    g_QT[((size_t)jb * 256 + d) * SEQ + s] = qn;
}

// ---------------- K6: raw = K @ Q^T (tiled batched GEMM) ----------------
#define TS 32
__global__ void k_raw() {
    int blk = blockIdx.x;         // jb*8 + stile
    int jb = blk >> 3;
    int s0 = (blk & 7) * TS;
    int tid = threadIdx.x;        // 256 (one per t)
    __shared__ float Ksh[TS][256];
    __shared__ float Qsh[8][256];
    const float* Kg = g_K  + (size_t)jb * SEQ * 256;
    const float* Qg = g_QT + (size_t)jb * 256 * SEQ;

    for (int idx = tid; idx < TS * 256; idx += 256)
        Ksh[idx >> 8][idx & 255] = Kg[(s0 + (idx >> 8)) * 256 + (idx & 255)];

    float acc[TS];
    #pragma unroll
    for (int r = 0; r < TS; r++) acc[r] = 0.f;

    for (int dc = 0; dc < 256; dc += 8) {
        __syncthreads();
        #pragma unroll
        for (int dd = 0; dd < 8; dd++) Qsh[dd][tid] = Qg[(dc + dd) * SEQ + tid];
        __syncthreads();
        #pragma unroll
        for (int dq = 0; dq < 8; dq += 4) {
            float q0 = Qsh[dq][tid], q1 = Qsh[dq + 1][tid];
            float q2 = Qsh[dq + 2][tid], q3 = Qsh[dq + 3][tid];
            #pragma unroll
            for (int r = 0; r < TS; r++) {
                float4 k4 = *(const float4*)&Ksh[r][dc + dq];
                acc[r] = fmaf(k4.x, q0, fmaf(k4.y, q1, fmaf(k4.z, q2, fmaf(k4.w, q3, acc[r]))));
            }
        }
    }
    float* Rg = g_raw + (size_t)jb * SEQ * SEQ;
    #pragma unroll
    for (int r = 0; r < TS; r++) Rg[(s0 + r) * SEQ + tid] = acc[r];
}

// ---------------- K7: softmax -> attn (in place) ----------------
__global__ void k_soft(const float* __restrict__ temp,
                       const float* __restrict__ alphas, const float* __restrict__ betas) {
    int blk = blockIdx.x;         // jb*256 + s
    int s = blk & 255, jb = blk >> 8, j = jb >> 3;
    int t = threadIdx.x;          // 256
    __shared__ float red[256];
    float tv = fabsf(temp[0]) + 1e-4f;
    float v = g_raw[((size_t)jb * SEQ + s) * SEQ + t] * (1.f / (16.f * tv));

    red[t] = v; __syncthreads();
    for (int st = 128; st; st >>= 1) { if (t < st) red[t] = fmaxf(red[t], red[t + st]); __syncthreads(); }
    float m = red[0]; __syncthreads();
    float e = expf(v - m);
    float sum = blk_sum(e, red, 256);
    float attn = fabsf(betas[j]) * e / sum + ((t == s) ? fabsf(alphas[j]) : 0.f);
    g_raw[((size_t)jb * SEQ + s) * SEQ + t] = attn;
}

// ---------------- K8: spatial + conv + epilogue -> outs ----------------
__global__ void k_spatial(float* __restrict__ out, const float* __restrict__ convk,
                          const float* __restrict__ thetas, const float* __restrict__ gammas) {
    int blk = blockIdx.x;         // jb*16 + tile
    int jb = blk >> 4;
    int s0 = (blk & 15) * 16;
    int j = jb >> 3, b = jb & 7;
    int bj = b * 8 + j;
    int tid = threadIdx.x;        // 256
    int f = tid & 63, tg = tid >> 6;
    __shared__ float Ash[16][256];
    __shared__ float Red[4][16][64];

    for (int idx = tid; idx < 16 * 256; idx += 256)
        Ash[idx >> 8][idx & 255] = g_raw[((size_t)jb * SEQ + s0 + (idx >> 8)) * SEQ + (idx & 255)];
    __syncthreads();

    const float* XP = out + OFF_PROJ + (size_t)bj * SEQ * FEAT;
    float acc[16];
    #pragma unroll
    for (int r = 0; r < 16; r++) acc[r] = 0.f;
    for (int t = tg * 64; t < tg * 64 + 64; t++) {
        float xp = XP[t * FEAT + f];
        #pragma unroll
        for (int r = 0; r < 16; r++) acc[r] = fmaf(Ash[r][t], xp, acc[r]);
    }
    #pragma unroll
    for (int r = 0; r < 16; r++) Red[tg][r][f] = acc[r];
    __syncthreads();

    float th = fabsf(thetas[j]);
    float ga = gammas[j];
    for (int idx = tid; idx < 16 * 64; idx += 256) {
        int r = idx >> 6, ff = idx & 63;
        float v = Red[0][r][ff] + Red[1][r][ff] + Red[2][r][ff] + Red[3][r][ff];
        int s = s0 + r;
        float w3 = 0.f;
        #pragma unroll
        for (int k = 0; k < KSZ; k++) {
            int tt = s + k - 7;
            if (tt >= 0 && tt < SEQ)
                w3 = fmaf(XP[tt * FEAT + ff], convk[(j * FEAT + ff) * KSZ + k], w3);
        }
        v += th * w3 + ga * g_comb[((size_t)bj * SEQ + s) * FEAT + ff];
        out[((size_t)bj * SEQ + s) * FEAT + ff] = v;
    }
}

// ---------------- launch ----------------
extern "C" void kernel_launch(void* const* d_in, const int* in_sizes, int n_in,
                              void* d_out, int out_size) {
    const float* x_in   = (const float*)d_in[0];
    const float* proj   = (const float*)d_in[1];
    const float* grid   = (const float*)d_in[2];
    const float* sw     = (const float*)d_in[3];
    const float* tau    = (const float*)d_in[4];
    const float* temp   = (const float*)d_in[5];
    const float* omiga  = (const float*)d_in[6];
    const float* W2s    = (const float*)d_in[7];
    const float* bs     = (const float*)d_in[8];
    const float* ln_w   = (const float*)d_in[9];
    const float* ln_b   = (const float*)d_in[10];
    const float* alphas = (const float*)d_in[11];
    const float* betas  = (const float*)d_in[12];
    const float* thetas = (const float*)d_in[13];
    const float* gammas = (const float*)d_in[14];
    const float* convk  = (const float*)d_in[15];
    float* out = (float*)d_out;

    k_stats   <<<Bb * IN_N, FEAT>>>(x_in);
    k_act     <<<Bb * IN_N, 256>>>(x_in, grid, sw, omiga);
    k_maskmult<<<1, Bb * IN_N * OUT_N>>>(tau, temp);
    k_comb    <<<Bb * OUT_N * SEQ, FEAT>>>(out, ln_w, ln_b, W2s, bs);
    k_kq      <<<OUT_N * Bb * SEQ, 256>>>(proj);
    k_raw     <<<OUT_N * Bb * (SEQ / TS), 256>>>();
    k_soft    <<<OUT_N * Bb * SEQ, 256>>>(temp, alphas, betas);
    k_spatial <<<OUT_N * Bb * (SEQ / 16), 256>>>(out, convk, thetas, gammas);
}

// round 2
// speedup vs baseline: 1.5466x; 1.5466x over previous
#include <cuda_runtime.h>
#include <math.h>

#define Bb 8
#define IN_N 8
#define OUT_N 8
#define SEQ 256
#define FEAT 64
#define NCg 99
#define KSZ 15

// ---------------- scratch ----------------
__device__ float g_mu[Bb*IN_N*FEAT];
__device__ float g_rinv[Bb*IN_N*FEAT];
__device__ float g_epart[Bb*IN_N*4*OUT_N];           // energy partials [bi][st][o]
__device__ float g_comb[Bb*OUT_N*SEQ*FEAT];          // 4 MB
__device__ float g_xn [Bb*OUT_N*SEQ*FEAT];           // 4 MB  LN(combined)
__device__ float g_K [OUT_N*Bb*SEQ*256];             // 16 MB  [jb][s][d]
__device__ float g_Q [OUT_N*Bb*SEQ*256];             // 16 MB  [jb][t][d]
__device__ float g_raw[OUT_N*Bb*SEQ*SEQ];            // 16 MB

#define OFF_PROJ (Bb*OUT_N*SEQ*FEAT)

// ---------------- helpers ----------------
__device__ __forceinline__ void basis4(float u, float* bv, int* ci) {
    int m = (int)floorf(u);
    #pragma unroll
    for (int k = 0; k < 4; k++) {
        int c = m - 1 + k;
        float val = 0.f;
        if (c >= 0 && c < NCg) {
            float d  = fabsf(u - (float)c);
            float r2 = fmaxf(2.f - d, 0.f);
            float r1 = fmaxf(1.f - d, 0.f);
            val = r2*r2*r2*(1.f/6.f) - r1*r1*r1*(4.f/6.f);
        }
        ci[k] = min(max(c, 0), NCg - 1);
        bv[k] = val;
    }
}

__device__ __forceinline__ void maskmult(int bi, int o, const float* tau, float tv,
                                         float* mask, float* mult) {
    float e = g_epart[(bi*4+0)*8+o] + g_epart[(bi*4+1)*8+o]
            + g_epart[(bi*4+2)*8+o] + g_epart[(bi*4+3)*8+o];
    float es = sqrtf(e * (1.f/16384.f) + 1e-8f);
    float ta = fabsf(tau[(bi & 7) * 8 + o]);
    *mask = 1.f / (1.f + expf(-(es - ta) / tv));
    *mult = es / (ta + 1e-8f);
}

// ---------------- K1: per-(b,i,f) stats over seq ----------------
__global__ void k_stats(const float* __restrict__ x) {
    int bi = blockIdx.x, tid = threadIdx.x;
    int f = tid & 63, q = tid >> 6;
    const float* p = x + (size_t)bi * SEQ * FEAT;
    float s = 0.f, s2 = 0.f;
    for (int t = q*64; t < q*64+64; t++) { float v = p[t*FEAT+f]; s += v; s2 = fmaf(v,v,s2); }
    __shared__ float ps[4][64], ps2[4][64];
    ps[q][f] = s; ps2[q][f] = s2; __syncthreads();
    if (q == 0) {
        float S  = ps[0][f]+ps[1][f]+ps[2][f]+ps[3][f];
        float S2 = ps2[0][f]+ps2[1][f]+ps2[2][f]+ps2[3][f];
        float mu = S * (1.f/256.f);
        float var = S2 * (1.f/256.f) - mu*mu;
        g_mu[bi*64+f] = mu;
        g_rinv[bi*64+f] = rsqrtf(var + 1e-5f);
    }
}

// ---------------- K2: partial energy (no act store) ----------------
__global__ void k_energy(const float* __restrict__ x, const float* __restrict__ sw,
                         const float* __restrict__ omiga) {
    int bx = blockIdx.x;
    int bi = bx >> 2, st = bx & 3, i = bi & 7;
    int tid = threadIdx.x;
    __shared__ float s_sw[OUT_N][NCg];
    __shared__ float s_om[OUT_N];
    __shared__ float wr[8][8];
    for (int oc = tid; oc < OUT_N*NCg; oc += 256)
        ((float*)s_sw)[oc] = sw[i*OUT_N*NCg + oc];
    if (tid < 8) s_om[tid] = fabsf(omiga[i*8 + tid]);
    __syncthreads();

    float eacc[8];
    #pragma unroll
    for (int o = 0; o < 8; o++) eacc[o] = 0.f;

    const float* xb = x + (size_t)bi * SEQ * FEAT + (size_t)st * 64 * FEAT;
    for (int e = tid; e < 64*FEAT; e += 256) {
        int f = e & 63;
        float xv = xb[e];
        float xn = (xv - g_mu[bi*64+f]) * g_rinv[bi*64+f] * 0.5f;
        xn = fminf(fmaxf(xn, -0.99f), 0.99f);
        float u = (xn + 1.f) * 49.f;
        float bv[4]; int ci[4];
        basis4(u, bv, ci);
        #pragma unroll
        for (int o = 0; o < 8; o++) {
            float a = s_om[o] * xv;
            #pragma unroll
            for (int k = 0; k < 4; k++) a = fmaf(bv[k], s_sw[o][ci[k]], a);
            eacc[o] = fmaf(a, a, eacc[o]);
        }
    }
    #pragma unroll
    for (int o = 0; o < 8; o++)
        for (int off = 16; off; off >>= 1)
            eacc[o] += __shfl_xor_sync(0xffffffffu, eacc[o], off);
    int w = tid >> 5, lane = tid & 31;
    if (lane == 0)
        for (int o = 0; o < 8; o++) wr[w][o] = eacc[o];
    __syncthreads();
    if (tid < 8) {
        float s = 0.f;
        for (int ww = 0; ww < 8; ww++) s += wr[ww][tid];
        g_epart[bx*8 + tid] = s;
    }
}

// ---------------- K3: combined (recompute act) + LN ----------------
__global__ void k_comb(const float* __restrict__ x, const float* __restrict__ sw,
                       const float* __restrict__ omiga, const float* __restrict__ tau,
                       const float* __restrict__ temp,
                       const float* __restrict__ ln_w, const float* __restrict__ ln_b) {
    int bx = blockIdx.x;
    int b = bx >> 6, st = bx & 63;
    int tid = threadIdx.x;
    int f = tid & 63, sl = tid >> 6;
    int s = st*4 + sl;
    __shared__ float s_sw[IN_N][OUT_N][NCg];
    __shared__ float s_om[IN_N][OUT_N];
    __shared__ float s_mask[IN_N][OUT_N];
    __shared__ float s_mu[IN_N][64], s_ri[IN_N][64];
    __shared__ float s_lnw[OUT_N][64], s_lnb[OUT_N][64];
    __shared__ float wsum[8][8], wsq[8][8];

    for (int t = tid; t < IN_N*OUT_N*NCg; t += 256) ((float*)s_sw)[t] = sw[t];
    if (tid < 64) {
        int i = tid >> 3, o = tid & 7;
        s_om[i][o] = fabsf(omiga[tid]);
        float tv = fabsf(temp[0]) + 1e-4f;
        float mk, ml;
        maskmult(b*8+i, o, tau, tv, &mk, &ml);
        s_mask[i][o] = mk;
    }
    for (int t = tid; t < 512; t += 256) {
        int i = t >> 6, ff = t & 63;
        s_mu[i][ff] = g_mu[(b*8+i)*64+ff];
        s_ri[i][ff] = g_rinv[(b*8+i)*64+ff];
        ((float*)s_lnw)[t] = ln_w[t];
        ((float*)s_lnb)[t] = ln_b[t];
    }
    __syncthreads();

    float comb[8];
    #pragma unroll
    for (int j = 0; j < 8; j++) comb[j] = 0.f;

    #pragma unroll
    for (int i = 0; i < 8; i++) {
        float xv = x[(((size_t)(b*8+i))*SEQ + s)*64 + f];
        float xn = (xv - s_mu[i][f]) * s_ri[i][f] * 0.5f;
        xn = fminf(fmaxf(xn, -0.99f), 0.99f);
        float u = (xn + 1.f) * 49.f;
        float bv[4]; int ci[4];
        basis4(u, bv, ci);
        #pragma unroll
        for (int j = 0; j < 8; j++) {
            float a = s_om[i][j] * xv;
            #pragma unroll
            for (int k = 0; k < 4; k++) a = fmaf(bv[k], s_sw[i][j][ci[k]], a);
            comb[j] = fmaf(s_mask[i][j], a, comb[j]);
        }
    }

    int w = tid >> 5, lane = tid & 31;
    #pragma unroll
    for (int j = 0; j < 8; j++) {
        float sm = comb[j], sq = comb[j]*comb[j];
        for (int off = 16; off; off >>= 1) {
            sm += __shfl_xor_sync(0xffffffffu, sm, off);
            sq += __shfl_xor_sync(0xffffffffu, sq, off);
        }
        if (lane == 0) { wsum[w][j] = sm; wsq[w][j] = sq; }
    }
    __syncthreads();
    #pragma unroll
    for (int j = 0; j < 8; j++) {
        float S = wsum[2*sl][j] + wsum[2*sl+1][j];
        float Q = wsq[2*sl][j] + wsq[2*sl+1][j];
        float mean = S * (1.f/64.f);
        float var = Q * (1.f/64.f) - mean*mean;
        float xn = (comb[j] - mean) * rsqrtf(var + 1e-5f) * s_lnw[j][f] + s_lnb[j][f];
        size_t base = (((size_t)(b*8+j))*SEQ + s)*64 + f;
        g_comb[base] = comb[j];
        g_xn[base] = xn;
    }
}

// ---------------- K4: x_prime = xn @ W2[j] + bs[j]  (W2 smem-resident) ----------------
__global__ void k_proj(float* __restrict__ out, const float* __restrict__ W2s,
                       const float* __restrict__ bsb) {
    int bx = blockIdx.x;
    int j = bx >> 4, rt = bx & 15;    // 128 rows per block over (b,s)=2048 rows
    int tid = threadIdx.x;
    __shared__ float Wsh[64][64];     // [k][f]
    __shared__ float Xsh[128][64];    // [row][k]
    const float* W2 = W2s + (size_t)j * 4096;
    for (int t = tid; t < 1024; t += 256)
        ((float4*)Wsh)[t] = ((const float4*)W2)[t];
    for (int t = tid; t < 2048; t += 256) {
        int r = t >> 4, c = t & 15;
        int rg2 = rt*128 + r; int b = rg2 >> 8, s = rg2 & 255;
        ((float4*)&Xsh[r][0])[c] =
            *(const float4*)&g_xn[(((size_t)(b*8+j))*SEQ + s)*64 + c*4];
    }
    __syncthreads();

    int c2 = tid & 31, rg = tid >> 5;
    int c0 = c2 * 2;
    float acc[16][2];
    #pragma unroll
    for (int r = 0; r < 16; r++) { acc[r][0] = 0.f; acc[r][1] = 0.f; }
    #pragma unroll 4
    for (int k = 0; k < 64; k++) {
        float2 wv = *(float2*)&Wsh[k][c0];
        #pragma unroll
        for (int r = 0; r < 16; r++) {
            float xv = Xsh[rg*16 + r][k];
            acc[r][0] = fmaf(xv, wv.x, acc[r][0]);
            acc[r][1] = fmaf(xv, wv.y, acc[r][1]);
        }
    }
    #pragma unroll
    for (int r = 0; r < 16; r++) {
        int rg2 = rt*128 + rg*16 + r; int b = rg2 >> 8, s = rg2 & 255;
        size_t o = OFF_PROJ + (((size_t)(b*8+j))*SEQ + s)*64;
        float2 bv = *(const float2*)&bsb[((size_t)j*SEQ + s)*64 + c0];
        float2 ov; ov.x = acc[r][0] + bv.x; ov.y = acc[r][1] + bv.y;
        *(float2*)&out[o + c0] = ov;
    }
}

// ---------------- K5: K/Q layernorm (both stored [s][d]) ----------------
__global__ void k_kq(const float* __restrict__ proj, const float* __restrict__ tau,
                     const float* __restrict__ temp) {
    int blk = blockIdx.x;
    int s = blk & 255, jb = blk >> 8;
    int j = jb >> 3, b = jb & 7;
    int d = threadIdx.x;
    int g = d >> 6, f = d & 63;
    __shared__ float wr[8][4];
    float tv = fabsf(temp[0]) + 1e-4f;
    int iK = 2*g, iQ = 2*g+1;
    float mkK, mlK, mkQ, mlQ;
    maskmult(b*8+iK, j, tau, tv, &mkK, &mlK);
    maskmult(b*8+iQ, j, tau, tv, &mkQ, &mlQ);
    float kv = proj[(((size_t)(b*8+iK))*SEQ + s)*64 + f] * mlK * mkK;
    float qv = proj[(((size_t)(b*8+iQ))*SEQ + s)*64 + f] * mlQ * mkQ;

    float a0 = kv, a1 = kv*kv, a2 = qv, a3 = qv*qv;
    for (int off = 16; off; off >>= 1) {
        a0 += __shfl_xor_sync(0xffffffffu, a0, off);
        a1 += __shfl_xor_sync(0xffffffffu, a1, off);
        a2 += __shfl_xor_sync(0xffffffffu, a2, off);
        a3 += __shfl_xor_sync(0xffffffffu, a3, off);
    }
    int w = d >> 5, lane = d & 31;
    if (lane == 0) { wr[w][0]=a0; wr[w][1]=a1; wr[w][2]=a2; wr[w][3]=a3; }
    __syncthreads();
    float ks=0.f, ks2=0.f, qs=0.f, qs2=0.f;
    #pragma unroll
    for (int ww = 0; ww < 8; ww++) { ks+=wr[ww][0]; ks2+=wr[ww][1]; qs+=wr[ww][2]; qs2+=wr[ww][3]; }
    float km = ks*(1.f/256.f), kvar = ks2*(1.f/256.f) - km*km;
    float qm = qs*(1.f/256.f), qvar = qs2*(1.f/256.f) - qm*qm;
    g_K[((size_t)jb*SEQ + s)*256 + d] = (kv - km) * rsqrtf(kvar + 1e-5f);
    g_Q[((size_t)jb*SEQ + s)*256 + d] = (qv - qm) * rsqrtf(qvar + 1e-5f);
}

// ---------------- K6: raw = K @ Q^T  (NT SGEMM, 128x128 tile, 8x8 micro) ----------------
#define PADK 132
__global__ void __launch_bounds__(256, 2) k_raw() {
    int bx = blockIdx.x;
    int jb = bx >> 2, tile = bx & 3;
    int s0 = (tile >> 1) * 128, t0 = (tile & 1) * 128;
    int tid = threadIdx.x;
    int tx = tid & 15, ty = tid >> 4;
    __shared__ float Ash[16*PADK];
    __shared__ float Bsh[16*PADK];
    const float* Kg = g_K + (size_t)jb * SEQ * 256;
    const float* Qg = g_Q + (size_t)jb * SEQ * 256;

    float acc[8][8];
    #pragma unroll
    for (int i = 0; i < 8; i++)
        #pragma unroll
        for (int jj = 0; jj < 8; jj++) acc[i][jj] = 0.f;

    for (int k0 = 0; k0 < 256; k0 += 16) {
        __syncthreads();
        #pragma unroll
        for (int l = 0; l < 2; l++) {
            int fi = tid*2 + l;
            int r = fi >> 2, c = fi & 3;
            float4 va = *(const float4*)&Kg[(size_t)(s0+r)*256 + k0 + c*4];
            Ash[(c*4+0)*PADK + r] = va.x; Ash[(c*4+1)*PADK + r] = va.y;
            Ash[(c*4+2)*PADK + r] = va.z; Ash[(c*4+3)*PADK + r] = va.w;
            float4 vb = *(const float4*)&Qg[(size_t)(t0+r)*256 + k0 + c*4];
            Bsh[(c*4+0)*PADK + r] = vb.x; Bsh[(c*4+1)*PADK + r] = vb.y;
            Bsh[(c*4+2)*PADK + r] = vb.z; Bsh[(c*4+3)*PADK + r] = vb.w;
        }
        __syncthreads();
        #pragma unroll
        for (int k = 0; k < 16; k++) {
            float4 a0 = *(float4*)&Ash[k*PADK + ty*8];
            float4 a1 = *(float4*)&Ash[k*PADK + ty*8 + 4];
            float4 b0 = *(float4*)&Bsh[k*PADK + tx*8];
            float4 b1 = *(float4*)&Bsh[k*PADK + tx*8 + 4];
            float av[8] = {a0.x,a0.y,a0.z,a0.w,a1.x,a1.y,a1.z,a1.w};
            float bw[8] = {b0.x,b0.y,b0.z,b0.w,b1.x,b1.y,b1.z,b1.w};
            #pragma unroll
            for (int i = 0; i < 8; i++)
                #pragma unroll
                for (int jj = 0; jj < 8; jj++)
                    acc[i][jj] = fmaf(av[i], bw[jj], acc[i][jj]);
        }
    }
    float* Rg = g_raw + (size_t)jb * SEQ * SEQ;
    #pragma unroll
    for (int i = 0; i < 8; i++) {
        float4 o0 = {acc[i][0], acc[i][1], acc[i][2], acc[i][3]};
        float4 o1 = {acc[i][4], acc[i][5], acc[i][6], acc[i][7]};
        *(float4*)&Rg[(size_t)(s0+ty*8+i)*256 + t0 + tx*8]     = o0;
        *(float4*)&Rg[(size_t)(s0+ty*8+i)*256 + t0 + tx*8 + 4] = o1;
    }
}

// ---------------- K7: fused softmax + spatial GEMM + conv + epilogue ----------------
__global__ void k_spatial(float* __restrict__ out, const float* __restrict__ convk,
                          const float* __restrict__ temp,
                          const float* __restrict__ alphas, const float* __restrict__ betas,
                          const float* __restrict__ thetas, const float* __restrict__ gammas) {
    int blk = blockIdx.x;
    int jb = blk >> 4;
    int s0 = (blk & 15) * 16;
    int j = jb >> 3, b = jb & 7;
    int bj = b*8 + j;
    int tid = threadIdx.x;
    __shared__ float Ash[16][256];
    __shared__ float Red[4][16][64];

    float inv = 1.f / (16.f * (fabsf(temp[0]) + 1e-4f));
    for (int idx = tid; idx < 16*256; idx += 256)
        Ash[idx>>8][idx&255] = g_raw[((size_t)jb*SEQ + s0 + (idx>>8))*SEQ + (idx&255)];
    __syncthreads();

    // softmax per row (16 lanes per row)
    {
        int rw = tid >> 4, c16 = tid & 15;
        float vloc[16];
        float m = -1e30f;
        #pragma unroll
        for (int k = 0; k < 16; k++) {
            vloc[k] = Ash[rw][c16*16 + k] * inv;
            m = fmaxf(m, vloc[k]);
        }
        for (int off = 8; off; off >>= 1) m = fmaxf(m, __shfl_xor_sync(0xffffffffu, m, off));
        float sum = 0.f;
        #pragma unroll
        for (int k = 0; k < 16; k++) { vloc[k] = expf(vloc[k] - m); sum += vloc[k]; }
        for (int off = 8; off; off >>= 1) sum += __shfl_xor_sync(0xffffffffu, sum, off);
        float sc = fabsf(betas[j]) / sum;
        float al = fabsf(alphas[j]);
        #pragma unroll
        for (int k = 0; k < 16; k++) {
            int t = c16*16 + k;
            float vv = vloc[k] * sc;
            if (t == s0 + rw) vv += al;
            Ash[rw][t] = vv;
        }
    }
    __syncthreads();

    int f = tid & 63, tg = tid >> 6;
    const float* XP = out + OFF_PROJ + (size_t)bj * SEQ * FEAT;
    float acc[16];
    #pragma unroll
    for (int r = 0; r < 16; r++) acc[r] = 0.f;
    for (int t = tg*64; t < tg*64 + 64; t++) {
        float xp = XP[t*FEAT + f];
        #pragma unroll
        for (int r = 0; r < 16; r++) acc[r] = fmaf(Ash[r][t], xp, acc[r]);
    }
    #pragma unroll
    for (int r = 0; r < 16; r++) Red[tg][r][f] = acc[r];
    __syncthreads();

    float th = fabsf(thetas[j]);
    float ga = gammas[j];
    for (int idx = tid; idx < 16*64; idx += 256) {
        int r = idx >> 6, ff = idx & 63;
        int s = s0 + r;
        float v = Red[0][r][ff] + Red[1][r][ff] + Red[2][r][ff] + Red[3][r][ff];
        float w3 = 0.f;
        #pragma unroll
        for (int k = 0; k < KSZ; k++) {
            int tt = s + k - 7;
            if (tt >= 0 && tt < SEQ)
                w3 = fmaf(XP[tt*FEAT + ff], convk[(j*FEAT + ff)*KSZ + k], w3);
        }
        v += th*w3 + ga * g_comb[((size_t)bj*SEQ + s)*64 + ff];
        out[((size_t)bj*SEQ + s)*64 + ff] = v;
    }
}

// ---------------- launch ----------------
extern "C" void kernel_launch(void* const* d_in, const int* in_sizes, int n_in,
                              void* d_out, int out_size) {
    const float* x_in   = (const float*)d_in[0];
    const float* proj   = (const float*)d_in[1];
    const float* sw     = (const float*)d_in[3];
    const float* tau    = (const float*)d_in[4];
    const float* temp   = (const float*)d_in[5];
    const float* omiga  = (const float*)d_in[6];
    const float* W2s    = (const float*)d_in[7];
    const float* bs     = (const float*)d_in[8];
    const float* ln_w   = (const float*)d_in[9];
    const float* ln_b   = (const float*)d_in[10];
    const float* alphas = (const float*)d_in[11];
    const float* betas  = (const float*)d_in[12];
    const float* thetas = (const float*)d_in[13];
    const float* gammas = (const float*)d_in[14];
    const float* convk  = (const float*)d_in[15];
    float* out = (float*)d_out;

    k_stats  <<<Bb*IN_N, 256>>>(x_in);
    k_energy <<<Bb*IN_N*4, 256>>>(x_in, sw, omiga);
    k_kq     <<<OUT_N*Bb*SEQ, 256>>>(proj, tau, temp);
    k_comb   <<<Bb*64, 256>>>(x_in, sw, omiga, tau, temp, ln_w, ln_b);
    k_proj   <<<OUT_N*16, 256>>>(out, W2s, bs);
    k_raw    <<<OUT_N*Bb*4, 256>>>();
    k_spatial<<<OUT_N*Bb*16, 256>>>(out, convk, temp, alphas, betas, thetas, gammas);
}

// round 3
// speedup vs baseline: 1.7575x; 1.1363x over previous
#include <cuda_runtime.h>
#include <math.h>

#define Bb 8
#define IN_N 8
#define OUT_N 8
#define SEQ 256
#define FEAT 64
#define NCg 99
#define KSZ 15

// ---------------- scratch ----------------
__device__ float g_mu[Bb*IN_N*FEAT];
__device__ float g_rinv[Bb*IN_N*FEAT];
__device__ float g_epart[Bb*IN_N*4*OUT_N];
__device__ float g_swT[IN_N*NCg*OUT_N];              // transposed weights [i][c][j]
__device__ float g_comb[Bb*OUT_N*SEQ*FEAT];
__device__ float g_xn [Bb*OUT_N*SEQ*FEAT];
__device__ float g_K [OUT_N*Bb*SEQ*256];
__device__ float g_Q [OUT_N*Bb*SEQ*256];
__device__ float g_raw[OUT_N*Bb*SEQ*SEQ];

#define OFF_PROJ (Bb*OUT_N*SEQ*FEAT)

// ---------------- helpers ----------------
__device__ __forceinline__ void basis4(float u, float* bv, int* ci) {
    int m = (int)floorf(u);
    #pragma unroll
    for (int k = 0; k < 4; k++) {
        int c = m - 1 + k;
        float val = 0.f;
        if (c >= 0 && c < NCg) {
            float d  = fabsf(u - (float)c);
            float r2 = fmaxf(2.f - d, 0.f);
            float r1 = fmaxf(1.f - d, 0.f);
            val = r2*r2*r2*(1.f/6.f) - r1*r1*r1*(4.f/6.f);
        }
        ci[k] = min(max(c, 0), NCg - 1);
        bv[k] = val;
    }
}

__device__ __forceinline__ void maskmult(int bi, int o, const float* tau, float tv,
                                         float* mask, float* mult) {
    float e = g_epart[(bi*4+0)*8+o] + g_epart[(bi*4+1)*8+o]
            + g_epart[(bi*4+2)*8+o] + g_epart[(bi*4+3)*8+o];
    float es = sqrtf(e * (1.f/16384.f) + 1e-8f);
    float ta = fabsf(tau[(bi & 7) * 8 + o]);
    *mask = 1.f / (1.f + expf(-(es - ta) / tv));
    *mult = es / (ta + 1e-8f);
}

// ---------------- K1: stats + weight transpose ----------------
__global__ void k_stats(const float* __restrict__ x, const float* __restrict__ sw) {
    int bx = blockIdx.x, tid = threadIdx.x;
    if (bx == 64) {
        for (int t = tid; t < IN_N*OUT_N*NCg; t += 256) {
            int i = t / (OUT_N*NCg);
            int rem = t - i*OUT_N*NCg;
            int o = rem / NCg, c = rem - o*NCg;
            g_swT[(i*NCg + c)*8 + o] = sw[t];
        }
        return;
    }
    int f = tid & 63, q = tid >> 6;
    const float* p = x + (size_t)bx * SEQ * FEAT;
    float s = 0.f, s2 = 0.f;
    for (int t = q*64; t < q*64+64; t++) { float v = p[t*FEAT+f]; s += v; s2 = fmaf(v,v,s2); }
    __shared__ float ps[4][64], ps2[4][64];
    ps[q][f] = s; ps2[q][f] = s2; __syncthreads();
    if (q == 0) {
        float S  = ps[0][f]+ps[1][f]+ps[2][f]+ps[3][f];
        float S2 = ps2[0][f]+ps2[1][f]+ps2[2][f]+ps2[3][f];
        float mu = S * (1.f/256.f);
        float var = S2 * (1.f/256.f) - mu*mu;
        g_mu[bx*64+f] = mu;
        g_rinv[bx*64+f] = rsqrtf(var + 1e-5f);
    }
}

// ---------------- K2: partial energy ----------------
__global__ void k_energy(const float* __restrict__ x, const float* __restrict__ omiga) {
    int bx = blockIdx.x;
    int bi = bx >> 2, st = bx & 3, i = bi & 7;
    int tid = threadIdx.x;
    __shared__ float s_swT[NCg*8];
    __shared__ float s_om[8];
    __shared__ float wr[8][8];
    for (int t = tid; t < NCg*2; t += 256)
        ((float4*)s_swT)[t] = ((const float4*)(g_swT + i*NCg*8))[t];
    if (tid < 8) s_om[tid] = fabsf(omiga[i*8 + tid]);
    __syncthreads();

    float eacc[8];
    #pragma unroll
    for (int o = 0; o < 8; o++) eacc[o] = 0.f;

    const float* xb = x + (size_t)bi * SEQ * FEAT + (size_t)st * 64 * FEAT;
    for (int e = tid; e < 64*FEAT; e += 256) {
        int f = e & 63;
        float xv = xb[e];
        float xn = (xv - g_mu[bi*64+f]) * g_rinv[bi*64+f] * 0.5f;
        xn = fminf(fmaxf(xn, -0.99f), 0.99f);
        float bv[4]; int ci[4];
        basis4((xn + 1.f) * 49.f, bv, ci);
        float a[8];
        #pragma unroll
        for (int o = 0; o < 8; o++) a[o] = s_om[o] * xv;
        #pragma unroll
        for (int k = 0; k < 4; k++) {
            float4 w0 = *(const float4*)&s_swT[ci[k]*8];
            float4 w1 = *(const float4*)&s_swT[ci[k]*8 + 4];
            a[0]=fmaf(bv[k],w0.x,a[0]); a[1]=fmaf(bv[k],w0.y,a[1]);
            a[2]=fmaf(bv[k],w0.z,a[2]); a[3]=fmaf(bv[k],w0.w,a[3]);
            a[4]=fmaf(bv[k],w1.x,a[4]); a[5]=fmaf(bv[k],w1.y,a[5]);
            a[6]=fmaf(bv[k],w1.z,a[6]); a[7]=fmaf(bv[k],w1.w,a[7]);
        }
        #pragma unroll
        for (int o = 0; o < 8; o++) eacc[o] = fmaf(a[o], a[o], eacc[o]);
    }
    #pragma unroll
    for (int o = 0; o < 8; o++)
        for (int off = 16; off; off >>= 1)
            eacc[o] += __shfl_xor_sync(0xffffffffu, eacc[o], off);
    int w = tid >> 5, lane = tid & 31;
    if (lane == 0)
        for (int o = 0; o < 8; o++) wr[w][o] = eacc[o];
    __syncthreads();
    if (tid < 8) {
        float s = 0.f;
        for (int ww = 0; ww < 8; ww++) s += wr[ww][tid];
        g_epart[bx*8 + tid] = s;
    }
}

// ---------------- K3: K/Q layernorm — proj read ONCE per (b,s) ----------------
__global__ void k_kq(const float* __restrict__ proj, const float* __restrict__ tau,
                     const float* __restrict__ temp) {
    int blk = blockIdx.x;           // b*256 + s
    int b = blk >> 8, s = blk & 255;
    int tid = threadIdx.x;          // 256, elements tid and tid+256 over (i,f)
    int i0 = tid >> 6, f = tid & 63;
    int i1 = i0 + 4;
    __shared__ float pS[8][2], pS2[8][2];
    __shared__ float sc[8][8];

    float tv = fabsf(temp[0]) + 1e-4f;
    if (tid < 64) {
        float mk, ml;
        maskmult(b*8 + (tid>>3), tid & 7, tau, tv, &mk, &ml);
        sc[tid>>3][tid&7] = mk * ml;
    }

    float v0 = proj[(((size_t)(b*8+i0))*SEQ + s)*64 + f];
    float v1 = proj[(((size_t)(b*8+i1))*SEQ + s)*64 + f];
    float r0 = v0, r0q = v0*v0, r1 = v1, r1q = v1*v1;
    for (int off = 16; off; off >>= 1) {
        r0  += __shfl_xor_sync(0xffffffffu, r0, off);
        r0q += __shfl_xor_sync(0xffffffffu, r0q, off);
        r1  += __shfl_xor_sync(0xffffffffu, r1, off);
        r1q += __shfl_xor_sync(0xffffffffu, r1q, off);
    }
    int half = (tid >> 5) & 1;
    if ((tid & 31) == 0) {
        pS[i0][half] = r0; pS2[i0][half] = r0q;
        pS[i1][half] = r1; pS2[i1][half] = r1q;
    }
    __syncthreads();

    float S[8], S2[8];
    #pragma unroll
    for (int i = 0; i < 8; i++) { S[i] = pS[i][0] + pS[i][1]; S2[i] = pS2[i][0] + pS2[i][1]; }

    int dK0 = (i0 >> 1) * 64 + f;   // destination d for element 0
    int dK1 = (i1 >> 1) * 64 + f;
    bool e0K = (i0 & 1) == 0, e1K = (i1 & 1) == 0;

    #pragma unroll
    for (int j = 0; j < 8; j++) {
        float sumK = 0.f, sqK = 0.f, sumQ = 0.f, sqQ = 0.f;
        #pragma unroll
        for (int g = 0; g < 4; g++) {
            float cK = sc[2*g][j], cQ = sc[2*g+1][j];
            sumK = fmaf(cK, S[2*g], sumK);   sqK = fmaf(cK*cK, S2[2*g], sqK);
            sumQ = fmaf(cQ, S[2*g+1], sumQ); sqQ = fmaf(cQ*cQ, S2[2*g+1], sqQ);
        }
        float mK = sumK*(1.f/256.f), rK = rsqrtf(sqK*(1.f/256.f) - mK*mK + 1e-5f);
        float mQ = sumQ*(1.f/256.f), rQ = rsqrtf(sqQ*(1.f/256.f) - mQ*mQ + 1e-5f);
        size_t base = (((size_t)(j*8 + b))*SEQ + s)*256;
        float w0 = v0 * sc[i0][j], w1 = v1 * sc[i1][j];
        if (e0K) g_K[base + dK0] = (w0 - mK) * rK;
        else     g_Q[base + dK0] = (w0 - mQ) * rQ;
        if (e1K) g_K[base + dK1] = (w1 - mK) * rK;
        else     g_Q[base + dK1] = (w1 - mQ) * rQ;
    }
}

// ---------------- K4: raw = K @ Q^T (double-buffered SGEMM) ----------------
#define PADK 132
__global__ void __launch_bounds__(256, 2) k_raw() {
    int bx = blockIdx.x;
    int jb = bx >> 2, tile = bx & 3;
    int s0 = (tile >> 1) * 128, t0 = (tile & 1) * 128;
    int tid = threadIdx.x;
    int tx = tid & 15, ty = tid >> 4;
    __shared__ float Ash[2][16*PADK];
    __shared__ float Bsh[2][16*PADK];
    const float* Kg = g_K + (size_t)jb * SEQ * 256;
    const float* Qg = g_Q + (size_t)jb * SEQ * 256;

    int lr = tid >> 1;              // row within tile (0..127)
    int lc = (tid & 1) * 2;         // float4 col pair (0 or 2)

    float acc[8][8];
    #pragma unroll
    for (int i = 0; i < 8; i++)
        #pragma unroll
        for (int jj = 0; jj < 8; jj++) acc[i][jj] = 0.f;

    // prologue: chunk 0
    {
        #pragma unroll
        for (int l = 0; l < 2; l++) {
            int c = lc + l;
            float4 va = *(const float4*)&Kg[(size_t)(s0+lr)*256 + c*4];
            float4 vb = *(const float4*)&Qg[(size_t)(t0+lr)*256 + c*4];
            Ash[0][(c*4+0)*PADK+lr]=va.x; Ash[0][(c*4+1)*PADK+lr]=va.y;
            Ash[0][(c*4+2)*PADK+lr]=va.z; Ash[0][(c*4+3)*PADK+lr]=va.w;
            Bsh[0][(c*4+0)*PADK+lr]=vb.x; Bsh[0][(c*4+1)*PADK+lr]=vb.y;
            Bsh[0][(c*4+2)*PADK+lr]=vb.z; Bsh[0][(c*4+3)*PADK+lr]=vb.w;
        }
    }
    __syncthreads();

    for (int ch = 0; ch < 16; ch++) {
        float4 pa[2], pb[2];
        if (ch < 15) {
            int k0 = (ch + 1) * 16;
            #pragma unroll
            for (int l = 0; l < 2; l++) {
                int c = lc + l;
                pa[l] = *(const float4*)&Kg[(size_t)(s0+lr)*256 + k0 + c*4];
                pb[l] = *(const float4*)&Qg[(size_t)(t0+lr)*256 + k0 + c*4];
            }
        }
        const float* As = Ash[ch & 1];
        const float* Bs = Bsh[ch & 1];
        #pragma unroll
        for (int k = 0; k < 16; k++) {
            float4 a0 = *(const float4*)&As[k*PADK + ty*8];
            float4 a1 = *(const float4*)&As[k*PADK + ty*8 + 4];
            float4 b0 = *(const float4*)&Bs[k*PADK + tx*8];
            float4 b1 = *(const float4*)&Bs[k*PADK + tx*8 + 4];
            float av[8] = {a0.x,a0.y,a0.z,a0.w,a1.x,a1.y,a1.z,a1.w};
            float bw[8] = {b0.x,b0.y,b0.z,b0.w,b1.x,b1.y,b1.z,b1.w};
            #pragma unroll
            for (int i = 0; i < 8; i++)
                #pragma unroll
                for (int jj = 0; jj < 8; jj++)
                    acc[i][jj] = fmaf(av[i], bw[jj], acc[i][jj]);
        }
        if (ch < 15) {
            __syncthreads();
            float* Aw = Ash[(ch + 1) & 1];
            float* Bw = Bsh[(ch + 1) & 1];
            #pragma unroll
            for (int l = 0; l < 2; l++) {
                int c = lc + l;
                Aw[(c*4+0)*PADK+lr]=pa[l].x; Aw[(c*4+1)*PADK+lr]=pa[l].y;
                Aw[(c*4+2)*PADK+lr]=pa[l].z; Aw[(c*4+3)*PADK+lr]=pa[l].w;
                Bw[(c*4+0)*PADK+lr]=pb[l].x; Bw[(c*4+1)*PADK+lr]=pb[l].y;
                Bw[(c*4+2)*PADK+lr]=pb[l].z; Bw[(c*4+3)*PADK+lr]=pb[l].w;
            }
            __syncthreads();
        }
    }
    float* Rg = g_raw + (size_t)jb * SEQ * SEQ;
    #pragma unroll
    for (int i = 0; i < 8; i++) {
        float4 o0 = {acc[i][0], acc[i][1], acc[i][2], acc[i][3]};
        float4 o1 = {acc[i][4], acc[i][5], acc[i][6], acc[i][7]};
        *(float4*)&Rg[(size_t)(s0+ty*8+i)*256 + t0 + tx*8]     = o0;
        *(float4*)&Rg[(size_t)(s0+ty*8+i)*256 + t0 + tx*8 + 4] = o1;
    }
}

// ---------------- K5: combined + LN ----------------
__global__ void k_comb(const float* __restrict__ x,
                       const float* __restrict__ omiga, const float* __restrict__ tau,
                       const float* __restrict__ temp,
                       const float* __restrict__ ln_w, const float* __restrict__ ln_b) {
    int bx = blockIdx.x;
    int b = bx >> 6, st = bx & 63;
    int tid = threadIdx.x;
    int f = tid & 63, sl = tid >> 6;
    int s = st*4 + sl;
    __shared__ float s_swT[IN_N*NCg*8];
    __shared__ float s_mo[IN_N][OUT_N];     // mask*|omiga|
    __shared__ float s_mask[IN_N][OUT_N];
    __shared__ float s_mu[IN_N][64], s_ri[IN_N][64];
    __shared__ float s_lnw[OUT_N][64], s_lnb[OUT_N][64];
    __shared__ float wsum[8][8], wsq[8][8];

    for (int t = tid; t < IN_N*NCg*2; t += 256)
        ((float4*)s_swT)[t] = ((const float4*)g_swT)[t];
    if (tid < 64) {
        int i = tid >> 3, o = tid & 7;
        float tv = fabsf(temp[0]) + 1e-4f;
        float mk, ml;
        maskmult(b*8+i, o, tau, tv, &mk, &ml);
        s_mask[i][o] = mk;
        s_mo[i][o] = mk * fabsf(omiga[tid]);
    }
    for (int t = tid; t < 512; t += 256) {
        int i = t >> 6, ff = t & 63;
        s_mu[i][ff] = g_mu[(b*8+i)*64+ff];
        s_ri[i][ff] = g_rinv[(b*8+i)*64+ff];
        ((float*)s_lnw)[t] = ln_w[t];
        ((float*)s_lnb)[t] = ln_b[t];
    }
    __syncthreads();

    float comb[8];
    #pragma unroll
    for (int j = 0; j < 8; j++) comb[j] = 0.f;

    #pragma unroll
    for (int i = 0; i < 8; i++) {
        float xv = x[(((size_t)(b*8+i))*SEQ + s)*64 + f];
        float xn = (xv - s_mu[i][f]) * s_ri[i][f] * 0.5f;
        xn = fminf(fmaxf(xn, -0.99f), 0.99f);
        float bv[4]; int ci[4];
        basis4((xn + 1.f) * 49.f, bv, ci);
        float t8[8];
        #pragma unroll
        for (int j = 0; j < 8; j++) t8[j] = 0.f;
        const float* wb = &s_swT[i*NCg*8];
        #pragma unroll
        for (int k = 0; k < 4; k++) {
            float4 w0 = *(const float4*)&wb[ci[k]*8];
            float4 w1 = *(const float4*)&wb[ci[k]*8 + 4];
            t8[0]=fmaf(bv[k],w0.x,t8[0]); t8[1]=fmaf(bv[k],w0.y,t8[1]);
            t8[2]=fmaf(bv[k],w0.z,t8[2]); t8[3]=fmaf(bv[k],w0.w,t8[3]);
            t8[4]=fmaf(bv[k],w1.x,t8[4]); t8[5]=fmaf(bv[k],w1.y,t8[5]);
            t8[6]=fmaf(bv[k],w1.z,t8[6]); t8[7]=fmaf(bv[k],w1.w,t8[7]);
        }
        #pragma unroll
        for (int j = 0; j < 8; j++)
            comb[j] += fmaf(s_mo[i][j], xv, s_mask[i][j] * t8[j]);
    }

    int w = tid >> 5, lane = tid & 31;
    #pragma unroll
    for (int j = 0; j < 8; j++) {
        float sm = comb[j], sq = comb[j]*comb[j];
        for (int off = 16; off; off >>= 1) {
            sm += __shfl_xor_sync(0xffffffffu, sm, off);
            sq += __shfl_xor_sync(0xffffffffu, sq, off);
        }
        if (lane == 0) { wsum[w][j] = sm; wsq[w][j] = sq; }
    }
    __syncthreads();
    #pragma unroll
    for (int j = 0; j < 8; j++) {
        float S = wsum[2*sl][j] + wsum[2*sl+1][j];
        float Q = wsq[2*sl][j] + wsq[2*sl+1][j];
        float mean = S * (1.f/64.f);
        float var = Q * (1.f/64.f) - mean*mean;
        float xn = (comb[j] - mean) * rsqrtf(var + 1e-5f) * s_lnw[j][f] + s_lnb[j][f];
        size_t base = (((size_t)(b*8+j))*SEQ + s)*64 + f;
        g_comb[base] = comb[j];
        g_xn[base] = xn;
    }
}

// ---------------- K6: x_prime GEMM ----------------
__global__ void k_proj(float* __restrict__ out, const float* __restrict__ W2s,
                       const float* __restrict__ bsb) {
    int bx = blockIdx.x;
    int j = bx >> 4, rt = bx & 15;
    int tid = threadIdx.x;
    __shared__ float Wsh[64][64];
    __shared__ float Xsh[128][64];
    const float* W2 = W2s + (size_t)j * 4096;
    for (int t = tid; t < 1024; t += 256)
        ((float4*)Wsh)[t] = ((const float4*)W2)[t];
    for (int t = tid; t < 2048; t += 256) {
        int r = t >> 4, c = t & 15;
        int rg2 = rt*128 + r; int b = rg2 >> 8, s = rg2 & 255;
        ((float4*)&Xsh[r][0])[c] =
            *(const float4*)&g_xn[(((size_t)(b*8+j))*SEQ + s)*64 + c*4];
    }
    __syncthreads();

    int c2 = tid & 31, rg = tid >> 5;
    int c0 = c2 * 2;
    float acc[16][2];
    #pragma unroll
    for (int r = 0; r < 16; r++) { acc[r][0] = 0.f; acc[r][1] = 0.f; }
    #pragma unroll 4
    for (int k = 0; k < 64; k++) {
        float2 wv = *(float2*)&Wsh[k][c0];
        #pragma unroll
        for (int r = 0; r < 16; r++) {
            float xv = Xsh[rg*16 + r][k];
            acc[r][0] = fmaf(xv, wv.x, acc[r][0]);
            acc[r][1] = fmaf(xv, wv.y, acc[r][1]);
        }
    }
    #pragma unroll
    for (int r = 0; r < 16; r++) {
        int rg2 = rt*128 + rg*16 + r; int b = rg2 >> 8, s = rg2 & 255;
        size_t o = OFF_PROJ + (((size_t)(b*8+j))*SEQ + s)*64;
        float2 bv = *(const float2*)&bsb[((size_t)j*SEQ + s)*64 + c0];
        float2 ov; ov.x = acc[r][0] + bv.x; ov.y = acc[r][1] + bv.y;
        *(float2*)&out[o + c0] = ov;
    }
}

// ---------------- K7: fused softmax + spatial + conv + epilogue ----------------
__global__ void k_spatial(float* __restrict__ out, const float* __restrict__ convk,
                          const float* __restrict__ temp,
                          const float* __restrict__ alphas, const float* __restrict__ betas,
                          const float* __restrict__ thetas, const float* __restrict__ gammas) {
    int blk = blockIdx.x;
    int jb = blk >> 4;
    int s0 = (blk & 15) * 16;
    int j = jb >> 3, b = jb & 7;
    int bj = b*8 + j;
    int tid = threadIdx.x;
    __shared__ float Ash[16][256];
    __shared__ float Red[4][16][64];

    float inv = 1.f / (16.f * (fabsf(temp[0]) + 1e-4f));
    for (int idx = tid; idx < 16*256; idx += 256)
        Ash[idx>>8][idx&255] = g_raw[((size_t)jb*SEQ + s0 + (idx>>8))*SEQ + (idx&255)];
    __syncthreads();

    {
        int rw = tid >> 4, c16 = tid & 15;
        float vloc[16];
        float m = -1e30f;
        #pragma unroll
        for (int k = 0; k < 16; k++) {
            vloc[k] = Ash[rw][c16*16 + k] * inv;
            m = fmaxf(m, vloc[k]);
        }
        for (int off = 8; off; off >>= 1) m = fmaxf(m, __shfl_xor_sync(0xffffffffu, m, off));
        float sum = 0.f;
        #pragma unroll
        for (int k = 0; k < 16; k++) { vloc[k] = expf(vloc[k] - m); sum += vloc[k]; }
        for (int off = 8; off; off >>= 1) sum += __shfl_xor_sync(0xffffffffu, sum, off);
        float sc = fabsf(betas[j]) / sum;
        float al = fabsf(alphas[j]);
        #pragma unroll
        for (int k = 0; k < 16; k++) {
            int t = c16*16 + k;
            float vv = vloc[k] * sc;
            if (t == s0 + rw) vv += al;
            Ash[rw][t] = vv;
        }
    }
    __syncthreads();

    int f = tid & 63, tg = tid >> 6;
    const float* XP = out + OFF_PROJ + (size_t)bj * SEQ * FEAT;
    float acc[16];
    #pragma unroll
    for (int r = 0; r < 16; r++) acc[r] = 0.f;
    for (int t = tg*64; t < tg*64 + 64; t++) {
        float xp = XP[t*FEAT + f];
        #pragma unroll
        for (int r = 0; r < 16; r++) acc[r] = fmaf(Ash[r][t], xp, acc[r]);
    }
    #pragma unroll
    for (int r = 0; r < 16; r++) Red[tg][r][f] = acc[r];
    __syncthreads();

    float th = fabsf(thetas[j]);
    float ga = gammas[j];
    for (int idx = tid; idx < 16*64; idx += 256) {
        int r = idx >> 6, ff = idx & 63;
        int s = s0 + r;
        float v = Red[0][r][ff] + Red[1][r][ff] + Red[2][r][ff] + Red[3][r][ff];
        float w3 = 0.f;
        #pragma unroll
        for (int k = 0; k < KSZ; k++) {
            int tt = s + k - 7;
            if (tt >= 0 && tt < SEQ)
                w3 = fmaf(XP[tt*FEAT + ff], convk[(j*FEAT + ff)*KSZ + k], w3);
        }
        v += th*w3 + ga * g_comb[((size_t)bj*SEQ + s)*64 + ff];
        out[((size_t)bj*SEQ + s)*64 + ff] = v;
    }
}

// ---------------- launch ----------------
extern "C" void kernel_launch(void* const* d_in, const int* in_sizes, int n_in,
                              void* d_out, int out_size) {
    const float* x_in   = (const float*)d_in[0];
    const float* proj   = (const float*)d_in[1];
    const float* sw     = (const float*)d_in[3];
    const float* tau    = (const float*)d_in[4];
    const float* temp   = (const float*)d_in[5];
    const float* omiga  = (const float*)d_in[6];
    const float* W2s    = (const float*)d_in[7];
    const float* bs     = (const float*)d_in[8];
    const float* ln_w   = (const float*)d_in[9];
    const float* ln_b   = (const float*)d_in[10];
    const float* alphas = (const float*)d_in[11];
    const float* betas  = (const float*)d_in[12];
    const float* thetas = (const float*)d_in[13];
    const float* gammas = (const float*)d_in[14];
    const float* convk  = (const float*)d_in[15];
    float* out = (float*)d_out;

    k_stats  <<<Bb*IN_N + 1, 256>>>(x_in, sw);
    k_energy <<<Bb*IN_N*4, 256>>>(x_in, omiga);
    k_kq     <<<Bb*SEQ, 256>>>(proj, tau, temp);
    k_raw    <<<OUT_N*Bb*4, 256>>>();                 // captured launch (index 3)
    k_comb   <<<Bb*64, 256>>>(x_in, omiga, tau, temp, ln_w, ln_b);
    k_proj   <<<OUT_N*16, 256>>>(out, W2s, bs);
    k_spatial<<<OUT_N*Bb*16, 256>>>(out, convk, temp, alphas, betas, thetas, gammas);
}

// round 5
// speedup vs baseline: 2.2508x; 1.2807x over previous
#include <cuda_runtime.h>
#include <math.h>
#include <stdint.h>

#define Bb 8
#define IN_N 8
#define OUT_N 8
#define SEQ 256
#define FEAT 64
#define NCg 99
#define KSZ 15

// ---------------- scratch ----------------
__device__ float g_mu[Bb*IN_N*FEAT];
__device__ float g_rinv[Bb*IN_N*FEAT];
__device__ float g_epart[Bb*IN_N*4*OUT_N];
__device__ float g_swT[IN_N*NCg*OUT_N];
__device__ float g_comb[Bb*OUT_N*SEQ*FEAT];
__device__ float g_xn [Bb*OUT_N*SEQ*FEAT];
__device__ float g_K [OUT_N*Bb*SEQ*256];
__device__ float g_Q [OUT_N*Bb*SEQ*256];
__device__ float g_raw[OUT_N*Bb*SEQ*SEQ];

#define OFF_PROJ (Bb*OUT_N*SEQ*FEAT)

// ---------------- shared helpers ----------------
__device__ __forceinline__ void basis4(float u, float* bv, int* ci) {
    int m = (int)floorf(u);
    #pragma unroll
    for (int k = 0; k < 4; k++) {
        int c = m - 1 + k;
        float val = 0.f;
        if (c >= 0 && c < NCg) {
            float d  = fabsf(u - (float)c);
            float r2 = fmaxf(2.f - d, 0.f);
            float r1 = fmaxf(1.f - d, 0.f);
            val = r2*r2*r2*(1.f/6.f) - r1*r1*r1*(4.f/6.f);
        }
        ci[k] = min(max(c, 0), NCg - 1);
        bv[k] = val;
    }
}
__device__ __forceinline__ void maskmult(int bi, int o, const float* tau, float tv,
                                         float* mask, float* mult) {
    float e = g_epart[(bi*4+0)*8+o] + g_epart[(bi*4+1)*8+o]
            + g_epart[(bi*4+2)*8+o] + g_epart[(bi*4+3)*8+o];
    float es = sqrtf(e * (1.f/16384.f) + 1e-8f);
    float ta = fabsf(tau[(bi & 7) * 8 + o]);
    *mask = 1.f / (1.f + expf(-(es - ta) / tv));
    *mult = es / (ta + 1e-8f);
}
__device__ __forceinline__ uint32_t f2tf32(float x) {
    uint32_t u;
    asm("cvt.rna.tf32.f32 %0, %1;" : "=r"(u) : "f"(x));
    return u;
}

// ---------------- K1: stats + weight transpose ----------------
__global__ void k_stats(const float* __restrict__ x, const float* __restrict__ sw) {
    int bx = blockIdx.x, tid = threadIdx.x;
    if (bx == 64) {
        for (int t = tid; t < IN_N*OUT_N*NCg; t += 256) {
            int i = t / (OUT_N*NCg);
            int rem = t - i*OUT_N*NCg;
            int o = rem / NCg, c = rem - o*NCg;
            g_swT[(i*NCg + c)*8 + o] = sw[t];
        }
        return;
    }
    int f = tid & 63, q = tid >> 6;
    const float* p = x + (size_t)bx * SEQ * FEAT;
    float s = 0.f, s2 = 0.f;
    for (int t = q*64; t < q*64+64; t++) { float v = p[t*FEAT+f]; s += v; s2 = fmaf(v,v,s2); }
    __shared__ float ps[4][64], ps2[4][64];
    ps[q][f] = s; ps2[q][f] = s2; __syncthreads();
    if (q == 0) {
        float S  = ps[0][f]+ps[1][f]+ps[2][f]+ps[3][f];
        float S2 = ps2[0][f]+ps2[1][f]+ps2[2][f]+ps2[3][f];
        float mu = S * (1.f/256.f);
        float var = S2 * (1.f/256.f) - mu*mu;
        g_mu[bx*64+f] = mu;
        g_rinv[bx*64+f] = rsqrtf(var + 1e-5f);
    }
}

// ---------------- K2: partial energy ----------------
__global__ void k_energy(const float* __restrict__ x, const float* __restrict__ omiga) {
    int bx = blockIdx.x;
    int bi = bx >> 2, st = bx & 3, i = bi & 7;
    int tid = threadIdx.x;
    __shared__ float s_swT[NCg*8];
    __shared__ float s_om[8];
    __shared__ float wr[8][8];
    for (int t = tid; t < NCg*2; t += 256)
        ((float4*)s_swT)[t] = ((const float4*)(g_swT + i*NCg*8))[t];
    if (tid < 8) s_om[tid] = fabsf(omiga[i*8 + tid]);
    __syncthreads();

    float eacc[8];
    #pragma unroll
    for (int o = 0; o < 8; o++) eacc[o] = 0.f;

    const float* xb = x + (size_t)bi * SEQ * FEAT + (size_t)st * 64 * FEAT;
    for (int e = tid; e < 64*FEAT; e += 256) {
        int f = e & 63;
        float xv = xb[e];
        float xn = (xv - g_mu[bi*64+f]) * g_rinv[bi*64+f] * 0.5f;
        xn = fminf(fmaxf(xn, -0.99f), 0.99f);
        float bv[4]; int ci[4];
        basis4((xn + 1.f) * 49.f, bv, ci);
        float a[8];
        #pragma unroll
        for (int o = 0; o < 8; o++) a[o] = s_om[o] * xv;
        #pragma unroll
        for (int k = 0; k < 4; k++) {
            float4 w0 = *(const float4*)&s_swT[ci[k]*8];
            float4 w1 = *(const float4*)&s_swT[ci[k]*8 + 4];
            a[0]=fmaf(bv[k],w0.x,a[0]); a[1]=fmaf(bv[k],w0.y,a[1]);
            a[2]=fmaf(bv[k],w0.z,a[2]); a[3]=fmaf(bv[k],w0.w,a[3]);
            a[4]=fmaf(bv[k],w1.x,a[4]); a[5]=fmaf(bv[k],w1.y,a[5]);
            a[6]=fmaf(bv[k],w1.z,a[6]); a[7]=fmaf(bv[k],w1.w,a[7]);
        }
        #pragma unroll
        for (int o = 0; o < 8; o++) eacc[o] = fmaf(a[o], a[o], eacc[o]);
    }
    #pragma unroll
    for (int o = 0; o < 8; o++)
        for (int off = 16; off; off >>= 1)
            eacc[o] += __shfl_xor_sync(0xffffffffu, eacc[o], off);
    int w = tid >> 5, lane = tid & 31;
    if (lane == 0)
        for (int o = 0; o < 8; o++) wr[w][o] = eacc[o];
    __syncthreads();
    if (tid < 8) {
        float s = 0.f;
        for (int ww = 0; ww < 8; ww++) s += wr[ww][tid];
        g_epart[bx*8 + tid] = s;
    }
}

// ---------------- K3: K/Q layernorm ----------------
__global__ void k_kq(const float* __restrict__ proj, const float* __restrict__ tau,
                     const float* __restrict__ temp) {
    int blk = blockIdx.x;
    int b = blk >> 8, s = blk & 255;
    int tid = threadIdx.x;
    int i0 = tid >> 6, f = tid & 63;
    int i1 = i0 + 4;
    __shared__ float pS[8][2], pS2[8][2];
    __shared__ float sc[8][8];

    float tv = fabsf(temp[0]) + 1e-4f;
    if (tid < 64) {
        float mk, ml;
        maskmult(b*8 + (tid>>3), tid & 7, tau, tv, &mk, &ml);
        sc[tid>>3][tid&7] = mk * ml;
    }

    float v0 = proj[(((size_t)(b*8+i0))*SEQ + s)*64 + f];
    float v1 = proj[(((size_t)(b*8+i1))*SEQ + s)*64 + f];
    float r0 = v0, r0q = v0*v0, r1 = v1, r1q = v1*v1;
    for (int off = 16; off; off >>= 1) {
        r0  += __shfl_xor_sync(0xffffffffu, r0, off);
        r0q += __shfl_xor_sync(0xffffffffu, r0q, off);
        r1  += __shfl_xor_sync(0xffffffffu, r1, off);
        r1q += __shfl_xor_sync(0xffffffffu, r1q, off);
    }
    int half = (tid >> 5) & 1;
    if ((tid & 31) == 0) {
        pS[i0][half] = r0; pS2[i0][half] = r0q;
        pS[i1][half] = r1; pS2[i1][half] = r1q;
    }
    __syncthreads();

    float S[8], S2[8];
    #pragma unroll
    for (int i = 0; i < 8; i++) { S[i] = pS[i][0] + pS[i][1]; S2[i] = pS2[i][0] + pS2[i][1]; }

    int dK0 = (i0 >> 1) * 64 + f;
    int dK1 = (i1 >> 1) * 64 + f;
    bool e0K = (i0 & 1) == 0, e1K = (i1 & 1) == 0;

    #pragma unroll
    for (int j = 0; j < 8; j++) {
        float sumK = 0.f, sqK = 0.f, sumQ = 0.f, sqQ = 0.f;
        #pragma unroll
        for (int g = 0; g < 4; g++) {
            float cK = sc[2*g][j], cQ = sc[2*g+1][j];
            sumK = fmaf(cK, S[2*g], sumK);   sqK = fmaf(cK*cK, S2[2*g], sqK);
            sumQ = fmaf(cQ, S[2*g+1], sumQ); sqQ = fmaf(cQ*cQ, S2[2*g+1], sqQ);
        }
        float mK = sumK*(1.f/256.f), rK = rsqrtf(sqK*(1.f/256.f) - mK*mK + 1e-5f);
        float mQ = sumQ*(1.f/256.f), rQ = rsqrtf(sqQ*(1.f/256.f) - mQ*mQ + 1e-5f);
        size_t base = (((size_t)(j*8 + b))*SEQ + s)*256;
        float w0 = v0 * sc[i0][j], w1 = v1 * sc[i1][j];
        if (e0K) g_K[base + dK0] = (w0 - mK) * rK;
        else     g_Q[base + dK0] = (w0 - mQ) * rQ;
        if (e1K) g_K[base + dK1] = (w1 - mK) * rK;
        else     g_Q[base + dK1] = (w1 - mQ) * rQ;
    }
}

// ---------------- K4: raw = K @ Q^T via mma.sync tf32 ----------------
#define APAD 36
__global__ void __launch_bounds__(256) k_raw_tc() {
    int bx = blockIdx.x;            // jb*4 + tile
    int jb = bx >> 2;
    int m0 = ((bx >> 1) & 1) * 128, n0 = (bx & 1) * 128;
    __shared__ float sA[128*APAD];
    __shared__ float sB[128*APAD];
    const float* Kg = g_K + (size_t)jb * SEQ * 256;
    const float* Qg = g_Q + (size_t)jb * SEQ * 256;
    int tid = threadIdx.x, wid = tid >> 5, lane = tid & 31;
    int wm = (wid & 3) * 32, wn = (wid >> 2) * 64;
    int lr = lane >> 2, lc = lane & 3;

    float acc[2][8][4];
    #pragma unroll
    for (int i = 0; i < 2; i++)
        #pragma unroll
        for (int n = 0; n < 8; n++)
            #pragma unroll
            for (int q = 0; q < 4; q++) acc[i][n][q] = 0.f;

    for (int k0 = 0; k0 < 256; k0 += 32) {
        __syncthreads();
        #pragma unroll
        for (int l = 0; l < 4; l++) {
            int t = tid + l*256;        // 1024 float4 per matrix
            int row = t >> 3, c4 = t & 7;
            float4 v = *(const float4*)&Kg[(size_t)(m0+row)*256 + k0 + c4*4];
            uint4 tv;
            tv.x = f2tf32(v.x); tv.y = f2tf32(v.y); tv.z = f2tf32(v.z); tv.w = f2tf32(v.w);
            *(uint4*)&sA[row*APAD + c4*4] = tv;
            float4 w = *(const float4*)&Qg[(size_t)(n0+row)*256 + k0 + c4*4];
            uint4 tw;
            tw.x = f2tf32(w.x); tw.y = f2tf32(w.y); tw.z = f2tf32(w.z); tw.w = f2tf32(w.w);
            *(uint4*)&sB[row*APAD + c4*4] = tw;
        }
        __syncthreads();
        #pragma unroll
        for (int ks = 0; ks < 4; ks++) {
            int kk = ks * 8;
            uint32_t a[2][4];
            #pragma unroll
            for (int i = 0; i < 2; i++) {
                int r = wm + i*16 + lr;
                a[i][0] = __float_as_uint(sA[r*APAD + kk + lc]);
                a[i][1] = __float_as_uint(sA[(r+8)*APAD + kk + lc]);
                a[i][2] = __float_as_uint(sA[r*APAD + kk + lc + 4]);
                a[i][3] = __float_as_uint(sA[(r+8)*APAD + kk + lc + 4]);
            }
            uint32_t b[8][2];
            #pragma unroll
            for (int n = 0; n < 8; n++) {
                int c = wn + n*8 + lr;
                b[n][0] = __float_as_uint(sB[c*APAD + kk + lc]);
                b[n][1] = __float_as_uint(sB[c*APAD + kk + lc + 4]);
            }
            #pragma unroll
            for (int i = 0; i < 2; i++)
                #pragma unroll
                for (int n = 0; n < 8; n++) {
                    asm volatile(
                        "mma.sync.aligned.m16n8k8.row.col.f32.tf32.tf32.f32 "
                        "{%0,%1,%2,%3}, {%4,%5,%6,%7}, {%8,%9}, {%0,%1,%2,%3};"
                        : "+f"(acc[i][n][0]), "+f"(acc[i][n][1]),
                          "+f"(acc[i][n][2]), "+f"(acc[i][n][3])
                        : "r"(a[i][0]), "r"(a[i][1]), "r"(a[i][2]), "r"(a[i][3]),
                          "r"(b[n][0]), "r"(b[n][1]));
                }
        }
    }
    float* Rg = g_raw + (size_t)jb * SEQ * SEQ;
    #pragma unroll
    for (int i = 0; i < 2; i++)
        #pragma unroll
        for (int n = 0; n < 8; n++) {
            int r = m0 + wm + i*16 + lr;
            int c = n0 + wn + n*8 + 2*lc;
            float2 o0 = {acc[i][n][0], acc[i][n][1]};
            float2 o1 = {acc[i][n][2], acc[i][n][3]};
            *(float2*)&Rg[(size_t)r*256 + c]     = o0;
            *(float2*)&Rg[(size_t)(r+8)*256 + c] = o1;
        }
}

// ---------------- K5: combined + LN ----------------
__global__ void k_comb(const float* __restrict__ x,
                       const float* __restrict__ omiga, const float* __restrict__ tau,
                       const float* __restrict__ temp,
                       const float* __restrict__ ln_w, const float* __restrict__ ln_b) {
    int bx = blockIdx.x;
    int b = bx >> 6, st = bx & 63;
    int tid = threadIdx.x;
    int f = tid & 63, sl = tid >> 6;
    int s = st*4 + sl;
    __shared__ float s_swT[IN_N*NCg*8];
    __shared__ float s_mo[IN_N][OUT_N];
    __shared__ float s_mask[IN_N][OUT_N];
    __shared__ float s_mu[IN_N][64], s_ri[IN_N][64];
    __shared__ float s_lnw[OUT_N][64], s_lnb[OUT_N][64];
    __shared__ float wsum[8][8], wsq[8][8];

    for (int t = tid; t < IN_N*NCg*2; t += 256)
        ((float4*)s_swT)[t] = ((const float4*)g_swT)[t];
    if (tid < 64) {
        int i = tid >> 3, o = tid & 7;
        float tv = fabsf(temp[0]) + 1e-4f;
        float mk, ml;
        maskmult(b*8+i, o, tau, tv, &mk, &ml);
        s_mask[i][o] = mk;
        s_mo[i][o] = mk * fabsf(omiga[tid]);
    }
    for (int t = tid; t < 512; t += 256) {
        int i = t >> 6, ff = t & 63;
        s_mu[i][ff] = g_mu[(b*8+i)*64+ff];
        s_ri[i][ff] = g_rinv[(b*8+i)*64+ff];
        ((float*)s_lnw)[t] = ln_w[t];
        ((float*)s_lnb)[t] = ln_b[t];
    }
    __syncthreads();

    float comb[8];
    #pragma unroll
    for (int j = 0; j < 8; j++) comb[j] = 0.f;

    #pragma unroll
    for (int i = 0; i < 8; i++) {
        float xv = x[(((size_t)(b*8+i))*SEQ + s)*64 + f];
        float xn = (xv - s_mu[i][f]) * s_ri[i][f] * 0.5f;
        xn = fminf(fmaxf(xn, -0.99f), 0.99f);
        float bv[4]; int ci[4];
        basis4((xn + 1.f) * 49.f, bv, ci);
        float t8[8];
        #pragma unroll
        for (int j = 0; j < 8; j++) t8[j] = 0.f;
        const float* wb = &s_swT[i*NCg*8];
        #pragma unroll
        for (int k = 0; k < 4; k++) {
            float4 w0 = *(const float4*)&wb[ci[k]*8];
            float4 w1 = *(const float4*)&wb[ci[k]*8 + 4];
            t8[0]=fmaf(bv[k],w0.x,t8[0]); t8[1]=fmaf(bv[k],w0.y,t8[1]);
            t8[2]=fmaf(bv[k],w0.z,t8[2]); t8[3]=fmaf(bv[k],w0.w,t8[3]);
            t8[4]=fmaf(bv[k],w1.x,t8[4]); t8[5]=fmaf(bv[k],w1.y,t8[5]);
            t8[6]=fmaf(bv[k],w1.z,t8[6]); t8[7]=fmaf(bv[k],w1.w,t8[7]);
        }
        #pragma unroll
        for (int j = 0; j < 8; j++)
            comb[j] += fmaf(s_mo[i][j], xv, s_mask[i][j] * t8[j]);
    }

    int w = tid >> 5, lane = tid & 31;
    #pragma unroll
    for (int j = 0; j < 8; j++) {
        float sm = comb[j], sq = comb[j]*comb[j];
        for (int off = 16; off; off >>= 1) {
            sm += __shfl_xor_sync(0xffffffffu, sm, off);
            sq += __shfl_xor_sync(0xffffffffu, sq, off);
        }
        if (lane == 0) { wsum[w][j] = sm; wsq[w][j] = sq; }
    }
    __syncthreads();
    #pragma unroll
    for (int j = 0; j < 8; j++) {
        float S = wsum[2*sl][j] + wsum[2*sl+1][j];
        float Q = wsq[2*sl][j] + wsq[2*sl+1][j];
        float mean = S * (1.f/64.f);
        float var = Q * (1.f/64.f) - mean*mean;
        float xn = (comb[j] - mean) * rsqrtf(var + 1e-5f) * s_lnw[j][f] + s_lnb[j][f];
        size_t base = (((size_t)(b*8+j))*SEQ + s)*64 + f;
        g_comb[base] = comb[j];
        g_xn[base] = xn;
    }
}

// ---------------- K6: x_prime GEMM ----------------
__global__ void k_proj(float* __restrict__ out, const float* __restrict__ W2s,
                       const float* __restrict__ bsb) {
    int bx = blockIdx.x;
    int j = bx >> 4, rt = bx & 15;
    int tid = threadIdx.x;
    __shared__ float Wsh[64][64];
    __shared__ float Xsh[128][64];
    const float* W2 = W2s + (size_t)j * 4096;
    for (int t = tid; t < 1024; t += 256)
        ((float4*)Wsh)[t] = ((const float4*)W2)[t];
    for (int t = tid; t < 2048; t += 256) {
        int r = t >> 4, c = t & 15;
        int rg2 = rt*128 + r; int b = rg2 >> 8, s = rg2 & 255;
        ((float4*)&Xsh[r][0])[c] =
            *(const float4*)&g_xn[(((size_t)(b*8+j))*SEQ + s)*64 + c*4];
    }
    __syncthreads();

    int c2 = tid & 31, rg = tid >> 5;
    int c0 = c2 * 2;
    float acc[16][2];
    #pragma unroll
    for (int r = 0; r < 16; r++) { acc[r][0] = 0.f; acc[r][1] = 0.f; }
    #pragma unroll 4
    for (int k = 0; k < 64; k++) {
        float2 wv = *(float2*)&Wsh[k][c0];
        #pragma unroll
        for (int r = 0; r < 16; r++) {
            float xv = Xsh[rg*16 + r][k];
            acc[r][0] = fmaf(xv, wv.x, acc[r][0]);
            acc[r][1] = fmaf(xv, wv.y, acc[r][1]);
        }
    }
    #pragma unroll
    for (int r = 0; r < 16; r++) {
        int rg2 = rt*128 + rg*16 + r; int b = rg2 >> 8, s = rg2 & 255;
        size_t o = OFF_PROJ + (((size_t)(b*8+j))*SEQ + s)*64;
        float2 bv = *(const float2*)&bsb[((size_t)j*SEQ + s)*64 + c0];
        float2 ov; ov.x = acc[r][0] + bv.x; ov.y = acc[r][1] + bv.y;
        *(float2*)&out[o + c0] = ov;
    }
}

// ---------------- K7: fused softmax + spatial + conv + epilogue ----------------
__global__ void k_spatial(float* __restrict__ out, const float* __restrict__ convk,
                          const float* __restrict__ temp,
                          const float* __restrict__ alphas, const float* __restrict__ betas,
                          const float* __restrict__ thetas, const float* __restrict__ gammas) {
    int blk = blockIdx.x;
    int jb = blk >> 4;
    int s0 = (blk & 15) * 16;
    int j = jb >> 3, b = jb & 7;
    int bj = b*8 + j;
    int tid = threadIdx.x;
    __shared__ float Ash[16][256];
    __shared__ float Red[4][16][64];

    float inv = 1.f / (16.f * (fabsf(temp[0]) + 1e-4f));
    for (int idx = tid; idx < 16*256; idx += 256)
        Ash[idx>>8][idx&255] = g_raw[((size_t)jb*SEQ + s0 + (idx>>8))*SEQ + (idx&255)];
    __syncthreads();

    {
        int rw = tid >> 4, c16 = tid & 15;
        float vloc[16];
        float m = -1e30f;
        #pragma unroll
        for (int k = 0; k < 16; k++) {
            vloc[k] = Ash[rw][c16*16 + k] * inv;
            m = fmaxf(m, vloc[k]);
        }
        for (int off = 8; off; off >>= 1) m = fmaxf(m, __shfl_xor_sync(0xffffffffu, m, off));
        float sum = 0.f;
        #pragma unroll
        for (int k = 0; k < 16; k++) { vloc[k] = expf(vloc[k] - m); sum += vloc[k]; }
        for (int off = 8; off; off >>= 1) sum += __shfl_xor_sync(0xffffffffu, sum, off);
        float sc = fabsf(betas[j]) / sum;
        float al = fabsf(alphas[j]);
        #pragma unroll
        for (int k = 0; k < 16; k++) {
            int t = c16*16 + k;
            float vv = vloc[k] * sc;
            if (t == s0 + rw) vv += al;
            Ash[rw][t] = vv;
        }
    }
    __syncthreads();

    int f = tid & 63, tg = tid >> 6;
    const float* XP = out + OFF_PROJ + (size_t)bj * SEQ * FEAT;
    float acc[16];
    #pragma unroll
    for (int r = 0; r < 16; r++) acc[r] = 0.f;
    for (int t = tg*64; t < tg*64 + 64; t++) {
        float xp = XP[t*FEAT + f];
        #pragma unroll
        for (int r = 0; r < 16; r++) acc[r] = fmaf(Ash[r][t], xp, acc[r]);
    }
    #pragma unroll
    for (int r = 0; r < 16; r++) Red[tg][r][f] = acc[r];
    __syncthreads();

    float th = fabsf(thetas[j]);
    float ga = gammas[j];
    for (int idx = tid; idx < 16*64; idx += 256) {
        int r = idx >> 6, ff = idx & 63;
        int s = s0 + r;
        float v = Red[0][r][ff] + Red[1][r][ff] + Red[2][r][ff] + Red[3][r][ff];
        float w3 = 0.f;
        #pragma unroll
        for (int k = 0; k < KSZ; k++) {
            int tt = s + k - 7;
            if (tt >= 0 && tt < SEQ)
                w3 = fmaf(XP[tt*FEAT + ff], convk[(j*FEAT + ff)*KSZ + k], w3);
        }
        v += th*w3 + ga * g_comb[((size_t)bj*SEQ + s)*64 + ff];
        out[((size_t)bj*SEQ + s)*64 + ff] = v;
    }
}

// ---------------- launch ----------------
extern "C" void kernel_launch(void* const* d_in, const int* in_sizes, int n_in,
                              void* d_out, int out_size) {
    const float* x_in   = (const float*)d_in[0];
    const float* proj   = (const float*)d_in[1];
    const float* sw     = (const float*)d_in[3];
    const float* tau    = (const float*)d_in[4];
    const float* temp   = (const float*)d_in[5];
    const float* omiga  = (const float*)d_in[6];
    const float* W2s    = (const float*)d_in[7];
    const float* bs     = (const float*)d_in[8];
    const float* ln_w   = (const float*)d_in[9];
    const float* ln_b   = (const float*)d_in[10];
    const float* alphas = (const float*)d_in[11];
    const float* betas  = (const float*)d_in[12];
    const float* thetas = (const float*)d_in[13];
    const float* gammas = (const float*)d_in[14];
    const float* convk  = (const float*)d_in[15];
    float* out = (float*)d_out;

    k_stats  <<<Bb*IN_N + 1, 256>>>(x_in, sw);
    k_energy <<<Bb*IN_N*4, 256>>>(x_in, omiga);
    k_kq     <<<Bb*SEQ, 256>>>(proj, tau, temp);
    k_raw_tc <<<OUT_N*Bb*4, 256>>>();                 // captured launch (index 3)
    k_comb   <<<Bb*64, 256>>>(x_in, omiga, tau, temp, ln_w, ln_b);
    k_proj   <<<OUT_N*16, 256>>>(out, W2s, bs);
    k_spatial<<<OUT_N*Bb*16, 256>>>(out, convk, temp, alphas, betas, thetas, gammas);
}

// round 6
// speedup vs baseline: 2.3078x; 1.0254x over previous
#include <cuda_runtime.h>
#include <cuda_fp16.h>
#include <math.h>
#include <stdint.h>

#define Bb 8
#define IN_N 8
#define OUT_N 8
#define SEQ 256
#define FEAT 64
#define NCg 99
#define KSZ 15

// ---------------- scratch ----------------
__device__ float g_mu[Bb*IN_N*FEAT];
__device__ float g_rinv[Bb*IN_N*FEAT];
__device__ float g_energy[Bb*IN_N*OUT_N];
__device__ float g_swT[IN_N*NCg*OUT_N];
__device__ float g_comb[Bb*OUT_N*SEQ*FEAT];
__device__ float g_xn [Bb*OUT_N*SEQ*FEAT];
__device__ __half g_K [OUT_N*Bb*SEQ*256];
__device__ __half g_Q [OUT_N*Bb*SEQ*256];
__device__ float g_raw[OUT_N*Bb*SEQ*SEQ];

#define OFF_PROJ (Bb*OUT_N*SEQ*FEAT)

// ---------------- helpers ----------------
__device__ __forceinline__ uint32_t smem_u32(const void* p) {
    uint32_t a;
    asm("{ .reg .u64 t; cvta.to.shared.u64 t, %1; cvt.u32.u64 %0, t; }" : "=r"(a) : "l"(p));
    return a;
}
__device__ __forceinline__ void basis4(float u, float* bv, int* ci) {
    int m = (int)floorf(u);
    #pragma unroll
    for (int k = 0; k < 4; k++) {
        int c = m - 1 + k;
        float val = 0.f;
        if (c >= 0 && c < NCg) {
            float d  = fabsf(u - (float)c);
            float r2 = fmaxf(2.f - d, 0.f);
            float r1 = fmaxf(1.f - d, 0.f);
            val = r2*r2*r2*(1.f/6.f) - r1*r1*r1*(4.f/6.f);
        }
        ci[k] = min(max(c, 0), NCg - 1);
        bv[k] = val;
    }
}
__device__ __forceinline__ void maskmult(int bi, int o, const float* tau, float tv,
                                         float* mask, float* mult) {
    float e = g_energy[bi*8+o];
    float es = sqrtf(e * (1.f/16384.f) + 1e-8f);
    float ta = fabsf(tau[(bi & 7) * 8 + o]);
    *mask = 1.f / (1.f + expf(-(es - ta) / tv));
    *mult = es / (ta + 1e-8f);
}

// ---------------- K0: fused stats + energy (+ weight transpose) ----------------
__global__ void k_statsE(const float* __restrict__ x, const float* __restrict__ sw,
                         const float* __restrict__ omiga) {
    int bx = blockIdx.x, tid = threadIdx.x;
    if (bx == 64) {
        for (int t = tid; t < IN_N*OUT_N*NCg; t += 256) {
            int i = t / (OUT_N*NCg);
            int rem = t - i*OUT_N*NCg;
            int o = rem / NCg, c = rem - o*NCg;
            g_swT[(i*NCg + c)*8 + o] = sw[t];
        }
        return;
    }
    int bi = bx, i = bi & 7;
    __shared__ float s_mu[64], s_ri[64];
    __shared__ float ps[4][64], ps2[4][64];
    __shared__ float s_swT[NCg*8];
    __shared__ float s_om[8];
    __shared__ float wr[8][8];
    int f = tid & 63, q = tid >> 6;
    const float* p = x + (size_t)bi * SEQ * FEAT;
    float s = 0.f, s2 = 0.f;
    for (int t = q*64; t < q*64+64; t++) { float v = p[t*64+f]; s += v; s2 = fmaf(v,v,s2); }
    ps[q][f] = s; ps2[q][f] = s2;
    for (int t = tid; t < NCg*8; t += 256) {
        int c = t >> 3, o = t & 7;
        s_swT[t] = sw[i*OUT_N*NCg + o*NCg + c];
    }
    if (tid < 8) s_om[tid] = fabsf(omiga[i*8 + tid]);
    __syncthreads();
    if (q == 0) {
        float S  = ps[0][f]+ps[1][f]+ps[2][f]+ps[3][f];
        float S2 = ps2[0][f]+ps2[1][f]+ps2[2][f]+ps2[3][f];
        float mu = S * (1.f/256.f);
        float var = S2 * (1.f/256.f) - mu*mu;
        float ri = rsqrtf(var + 1e-5f);
        s_mu[f] = mu; s_ri[f] = ri;
        g_mu[bi*64+f] = mu; g_rinv[bi*64+f] = ri;
    }
    __syncthreads();

    float eacc[8];
    #pragma unroll
    for (int o = 0; o < 8; o++) eacc[o] = 0.f;
    for (int e = tid; e < SEQ*FEAT; e += 256) {
        int ff = e & 63;
        float xv = p[e];
        float xn = (xv - s_mu[ff]) * s_ri[ff] * 0.5f;
        xn = fminf(fmaxf(xn, -0.99f), 0.99f);
        float bv[4]; int ci[4];
        basis4((xn + 1.f) * 49.f, bv, ci);
        float a[8];
        #pragma unroll
        for (int o = 0; o < 8; o++) a[o] = s_om[o] * xv;
        #pragma unroll
        for (int k = 0; k < 4; k++) {
            float4 w0 = *(const float4*)&s_swT[ci[k]*8];
            float4 w1 = *(const float4*)&s_swT[ci[k]*8 + 4];
            a[0]=fmaf(bv[k],w0.x,a[0]); a[1]=fmaf(bv[k],w0.y,a[1]);
            a[2]=fmaf(bv[k],w0.z,a[2]); a[3]=fmaf(bv[k],w0.w,a[3]);
            a[4]=fmaf(bv[k],w1.x,a[4]); a[5]=fmaf(bv[k],w1.y,a[5]);
            a[6]=fmaf(bv[k],w1.z,a[6]); a[7]=fmaf(bv[k],w1.w,a[7]);
        }
        #pragma unroll
        for (int o = 0; o < 8; o++) eacc[o] = fmaf(a[o], a[o], eacc[o]);
    }
    #pragma unroll
    for (int o = 0; o < 8; o++)
        for (int off = 16; off; off >>= 1)
            eacc[o] += __shfl_xor_sync(0xffffffffu, eacc[o], off);
    int w = tid >> 5, lane = tid & 31;
    if (lane == 0)
        for (int o = 0; o < 8; o++) wr[w][o] = eacc[o];
    __syncthreads();
    if (tid < 8) {
        float sm = 0.f;
        for (int ww = 0; ww < 8; ww++) sm += wr[ww][tid];
        g_energy[bi*8 + tid] = sm;
    }
}

// ---------------- K1: K/Q layernorm -> half ----------------
__global__ void k_kq(const float* __restrict__ proj, const float* __restrict__ tau,
                     const float* __restrict__ temp) {
    int blk = blockIdx.x;
    int b = blk >> 8, s = blk & 255;
    int tid = threadIdx.x;
    int i0 = tid >> 6, f = tid & 63;
    int i1 = i0 + 4;
    __shared__ float pS[8][2], pS2[8][2];
    __shared__ float sc[8][8];

    float tv = fabsf(temp[0]) + 1e-4f;
    if (tid < 64) {
        float mk, ml;
        maskmult(b*8 + (tid>>3), tid & 7, tau, tv, &mk, &ml);
        sc[tid>>3][tid&7] = mk * ml;
    }

    float v0 = proj[(((size_t)(b*8+i0))*SEQ + s)*64 + f];
    float v1 = proj[(((size_t)(b*8+i1))*SEQ + s)*64 + f];
    float r0 = v0, r0q = v0*v0, r1 = v1, r1q = v1*v1;
    for (int off = 16; off; off >>= 1) {
        r0  += __shfl_xor_sync(0xffffffffu, r0, off);
        r0q += __shfl_xor_sync(0xffffffffu, r0q, off);
        r1  += __shfl_xor_sync(0xffffffffu, r1, off);
        r1q += __shfl_xor_sync(0xffffffffu, r1q, off);
    }
    int half_ = (tid >> 5) & 1;
    if ((tid & 31) == 0) {
        pS[i0][half_] = r0; pS2[i0][half_] = r0q;
        pS[i1][half_] = r1; pS2[i1][half_] = r1q;
    }
    __syncthreads();

    float S[8], S2[8];
    #pragma unroll
    for (int i = 0; i < 8; i++) { S[i] = pS[i][0] + pS[i][1]; S2[i] = pS2[i][0] + pS2[i][1]; }

    int dK0 = (i0 >> 1) * 64 + f;
    int dK1 = (i1 >> 1) * 64 + f;
    bool e0K = (i0 & 1) == 0, e1K = (i1 & 1) == 0;

    #pragma unroll
    for (int j = 0; j < 8; j++) {
        float sumK = 0.f, sqK = 0.f, sumQ = 0.f, sqQ = 0.f;
        #pragma unroll
        for (int g = 0; g < 4; g++) {
            float cK = sc[2*g][j], cQ = sc[2*g+1][j];
            sumK = fmaf(cK, S[2*g], sumK);   sqK = fmaf(cK*cK, S2[2*g], sqK);
            sumQ = fmaf(cQ, S[2*g+1], sumQ); sqQ = fmaf(cQ*cQ, S2[2*g+1], sqQ);
        }
        float mK = sumK*(1.f/256.f), rK = rsqrtf(sqK*(1.f/256.f) - mK*mK + 1e-5f);
        float mQ = sumQ*(1.f/256.f), rQ = rsqrtf(sqQ*(1.f/256.f) - mQ*mQ + 1e-5f);
        size_t base = (((size_t)(j*8 + b))*SEQ + s)*256;
        float w0 = v0 * sc[i0][j], w1 = v1 * sc[i1][j];
        if (e0K) g_K[base + dK0] = __float2half_rn((w0 - mK) * rK);
        else     g_Q[base + dK0] = __float2half_rn((w0 - mQ) * rQ);
        if (e1K) g_K[base + dK1] = __float2half_rn((w1 - mK) * rK);
        else     g_Q[base + dK1] = __float2half_rn((w1 - mQ) * rQ);
    }
}

// ---------------- K2: combined + LN ----------------
__global__ void k_comb(const float* __restrict__ x,
                       const float* __restrict__ omiga, const float* __restrict__ tau,
                       const float* __restrict__ temp,
                       const float* __restrict__ ln_w, const float* __restrict__ ln_b) {
    int bx = blockIdx.x;
    int b = bx >> 6, st = bx & 63;
    int tid = threadIdx.x;
    int f = tid & 63, sl = tid >> 6;
    int s = st*4 + sl;
    __shared__ float s_swT[IN_N*NCg*8];
    __shared__ float s_mo[IN_N][OUT_N];
    __shared__ float s_mask[IN_N][OUT_N];
    __shared__ float s_mu[IN_N][64], s_ri[IN_N][64];
    __shared__ float s_lnw[OUT_N][64], s_lnb[OUT_N][64];
    __shared__ float wsum[8][8], wsq[8][8];

    for (int t = tid; t < IN_N*NCg*2; t += 256)
        ((float4*)s_swT)[t] = ((const float4*)g_swT)[t];
    if (tid < 64) {
        int i = tid >> 3, o = tid & 7;
        float tv = fabsf(temp[0]) + 1e-4f;
        float mk, ml;
        maskmult(b*8+i, o, tau, tv, &mk, &ml);
        s_mask[i][o] = mk;
        s_mo[i][o] = mk * fabsf(omiga[tid]);
    }
    for (int t = tid; t < 512; t += 256) {
        int i = t >> 6, ff = t & 63;
        s_mu[i][ff] = g_mu[(b*8+i)*64+ff];
        s_ri[i][ff] = g_rinv[(b*8+i)*64+ff];
        ((float*)s_lnw)[t] = ln_w[t];
        ((float*)s_lnb)[t] = ln_b[t];
    }
    __syncthreads();

    float comb[8];
    #pragma unroll
    for (int j = 0; j < 8; j++) comb[j] = 0.f;

    #pragma unroll
    for (int i = 0; i < 8; i++) {
        float xv = x[(((size_t)(b*8+i))*SEQ + s)*64 + f];
        float xn = (xv - s_mu[i][f]) * s_ri[i][f] * 0.5f;
        xn = fminf(fmaxf(xn, -0.99f), 0.99f);
        float bv[4]; int ci[4];
        basis4((xn + 1.f) * 49.f, bv, ci);
        float t8[8];
        #pragma unroll
        for (int j = 0; j < 8; j++) t8[j] = 0.f;
        const float* wb = &s_swT[i*NCg*8];
        #pragma unroll
        for (int k = 0; k < 4; k++) {
            float4 w0 = *(const float4*)&wb[ci[k]*8];
            float4 w1 = *(const float4*)&wb[ci[k]*8 + 4];
            t8[0]=fmaf(bv[k],w0.x,t8[0]); t8[1]=fmaf(bv[k],w0.y,t8[1]);
            t8[2]=fmaf(bv[k],w0.z,t8[2]); t8[3]=fmaf(bv[k],w0.w,t8[3]);
            t8[4]=fmaf(bv[k],w1.x,t8[4]); t8[5]=fmaf(bv[k],w1.y,t8[5]);
            t8[6]=fmaf(bv[k],w1.z,t8[6]); t8[7]=fmaf(bv[k],w1.w,t8[7]);
        }
        #pragma unroll
        for (int j = 0; j < 8; j++)
            comb[j] += fmaf(s_mo[i][j], xv, s_mask[i][j] * t8[j]);
    }

    int w = tid >> 5, lane = tid & 31;
    #pragma unroll
    for (int j = 0; j < 8; j++) {
        float sm = comb[j], sq = comb[j]*comb[j];
        for (int off = 16; off; off >>= 1) {
            sm += __shfl_xor_sync(0xffffffffu, sm, off);
            sq += __shfl_xor_sync(0xffffffffu, sq, off);
        }
        if (lane == 0) { wsum[w][j] = sm; wsq[w][j] = sq; }
    }
    __syncthreads();
    #pragma unroll
    for (int j = 0; j < 8; j++) {
        float S = wsum[2*sl][j] + wsum[2*sl+1][j];
        float Q = wsq[2*sl][j] + wsq[2*sl+1][j];
        float mean = S * (1.f/64.f);
        float var = Q * (1.f/64.f) - mean*mean;
        float xn = (comb[j] - mean) * rsqrtf(var + 1e-5f) * s_lnw[j][f] + s_lnb[j][f];
        size_t base = (((size_t)(b*8+j))*SEQ + s)*64 + f;
        g_comb[base] = comb[j];
        g_xn[base] = xn;
    }
}

// ---------------- K3: raw = K @ Q^T  (fp16 mma + cp.async double buffer) ----------------
#define HPAD 72
#define ABUF (128*HPAD)                 // halfs per A buffer
__global__ void __launch_bounds__(256, 2) k_raw_tc() {
    extern __shared__ __half sh[];
    int tid = threadIdx.x, wid = tid >> 5, lane = tid & 31;
    int bx = blockIdx.x;
    int jb = bx >> 2;
    int m0 = ((bx >> 1) & 1) * 128, n0 = (bx & 1) * 128;
    const __half* Kg = g_K + (size_t)jb * SEQ * 256;
    const __half* Qg = g_Q + (size_t)jb * SEQ * 256;
    int wm = (wid & 3) * 32, wn = (wid >> 2) * 64;
    int gr = lane >> 2, tg = lane & 3;
    uint32_t sbase = smem_u32(sh);

    float acc[2][8][4];
    #pragma unroll
    for (int i = 0; i < 2; i++)
        #pragma unroll
        for (int n = 0; n < 8; n++)
            #pragma unroll
            for (int q = 0; q < 4; q++) acc[i][n][q] = 0.f;

    auto issue = [&](int ch, int buf) {
        int k0 = ch * 64;
        #pragma unroll
        for (int l = 0; l < 4; l++) {
            int idx = tid + l*256;
            int row = idx >> 3, c = idx & 7;
            uint32_t da = sbase + (uint32_t)(buf*ABUF + row*HPAD + c*8) * 2;
            const __half* sa = Kg + (size_t)(m0+row)*256 + k0 + c*8;
            asm volatile("cp.async.ca.shared.global [%0], [%1], 16;" :: "r"(da), "l"(sa) : "memory");
            uint32_t db = sbase + (uint32_t)(2*ABUF + buf*ABUF + row*HPAD + c*8) * 2;
            const __half* sb = Qg + (size_t)(n0+row)*256 + k0 + c*8;
            asm volatile("cp.async.ca.shared.global [%0], [%1], 16;" :: "r"(db), "l"(sb) : "memory");
        }
        asm volatile("cp.async.commit_group;" ::: "memory");
    };

    issue(0, 0);
    #pragma unroll
    for (int ch = 0; ch < 4; ch++) {
        if (ch < 3) issue(ch+1, (ch+1)&1);
        if (ch < 3) asm volatile("cp.async.wait_group 1;" ::: "memory");
        else        asm volatile("cp.async.wait_group 0;" ::: "memory");
        __syncthreads();
        const __half* A = sh + (ch&1)*ABUF;
        const __half* B = sh + 2*ABUF + (ch&1)*ABUF;
        #pragma unroll
        for (int ks = 0; ks < 4; ks++) {
            int kk = ks * 16;
            uint32_t a[2][4];
            #pragma unroll
            for (int i = 0; i < 2; i++) {
                int r = wm + i*16 + gr;
                a[i][0] = *(const uint32_t*)&A[r*HPAD + kk + 2*tg];
                a[i][1] = *(const uint32_t*)&A[(r+8)*HPAD + kk + 2*tg];
                a[i][2] = *(const uint32_t*)&A[r*HPAD + kk + 8 + 2*tg];
                a[i][3] = *(const uint32_t*)&A[(r+8)*HPAD + kk + 8 + 2*tg];
            }
            uint32_t b[8][2];
            #pragma unroll
            for (int n = 0; n < 8; n++) {
                int cc = wn + n*8 + gr;
                b[n][0] = *(const uint32_t*)&B[cc*HPAD + kk + 2*tg];
                b[n][1] = *(const uint32_t*)&B[cc*HPAD + kk + 8 + 2*tg];
            }
            #pragma unroll
            for (int i = 0; i < 2; i++)
                #pragma unroll
                for (int n = 0; n < 8; n++) {
                    asm volatile(
                        "mma.sync.aligned.m16n8k16.row.col.f32.f16.f16.f32 "
                        "{%0,%1,%2,%3}, {%4,%5,%6,%7}, {%8,%9}, {%0,%1,%2,%3};"
                        : "+f"(acc[i][n][0]), "+f"(acc[i][n][1]),
                          "+f"(acc[i][n][2]), "+f"(acc[i][n][3])
                        : "r"(a[i][0]), "r"(a[i][1]), "r"(a[i][2]), "r"(a[i][3]),
                          "r"(b[n][0]), "r"(b[n][1]));
                }
        }
        __syncthreads();
    }
    float* Rg = g_raw + (size_t)jb * SEQ * SEQ;
    #pragma unroll
    for (int i = 0; i < 2; i++)
        #pragma unroll
        for (int n = 0; n < 8; n++) {
            int r = m0 + wm + i*16 + gr;
            int c = n0 + wn + n*8 + 2*tg;
            float2 o0 = {acc[i][n][0], acc[i][n][1]};
            float2 o1 = {acc[i][n][2], acc[i][n][3]};
            *(float2*)&Rg[(size_t)r*256 + c]     = o0;
            *(float2*)&Rg[(size_t)(r+8)*256 + c] = o1;
        }
}
#define RAW_SMEM (4*ABUF*2)

// ---------------- K4: x_prime GEMM ----------------
__global__ void k_proj(float* __restrict__ out, const float* __restrict__ W2s,
                       const float* __restrict__ bsb) {
    int bx = blockIdx.x;
    int j = bx >> 4, rt = bx & 15;
    int tid = threadIdx.x;
    __shared__ float Wsh[64][64];
    __shared__ float Xsh[128][64];
    const float* W2 = W2s + (size_t)j * 4096;
    for (int t = tid; t < 1024; t += 256)
        ((float4*)Wsh)[t] = ((const float4*)W2)[t];
    for (int t = tid; t < 2048; t += 256) {
        int r = t >> 4, c = t & 15;
        int rg2 = rt*128 + r; int b = rg2 >> 8, s = rg2 & 255;
        ((float4*)&Xsh[r][0])[c] =
            *(const float4*)&g_xn[(((size_t)(b*8+j))*SEQ + s)*64 + c*4];
    }
    __syncthreads();

    int c2 = tid & 31, rg = tid >> 5;
    int c0 = c2 * 2;
    float acc[16][2];
    #pragma unroll
    for (int r = 0; r < 16; r++) { acc[r][0] = 0.f; acc[r][1] = 0.f; }
    #pragma unroll 4
    for (int k = 0; k < 64; k++) {
        float2 wv = *(float2*)&Wsh[k][c0];
        #pragma unroll
        for (int r = 0; r < 16; r++) {
            float xv = Xsh[rg*16 + r][k];
            acc[r][0] = fmaf(xv, wv.x, acc[r][0]);
            acc[r][1] = fmaf(xv, wv.y, acc[r][1]);
        }
    }
    #pragma unroll
    for (int r = 0; r < 16; r++) {
        int rg2 = rt*128 + rg*16 + r; int b = rg2 >> 8, s = rg2 & 255;
        size_t o = OFF_PROJ + (((size_t)(b*8+j))*SEQ + s)*64;
        float2 bv = *(const float2*)&bsb[((size_t)j*SEQ + s)*64 + c0];
        float2 ov; ov.x = acc[r][0] + bv.x; ov.y = acc[r][1] + bv.y;
        *(float2*)&out[o + c0] = ov;
    }
}

// ---------------- K5: fused softmax + spatial + conv + epilogue (32-row tiles) ----------------
__global__ void k_spatial(float* __restrict__ out, const float* __restrict__ convk,
                          const float* __restrict__ temp,
                          const float* __restrict__ alphas, const float* __restrict__ betas,
                          const float* __restrict__ thetas, const float* __restrict__ gammas) {
    int blk = blockIdx.x;
    int jb = blk >> 3;
    int s0 = (blk & 7) * 32;
    int j = jb >> 3, b = jb & 7;
    int bj = b*8 + j;
    int tid = threadIdx.x;
    __shared__ float Ash[32][256];     // 32 KB
    __shared__ float s_ck[64*KSZ];

    float inv = 1.f / (16.f * (fabsf(temp[0]) + 1e-4f));
    for (int idx = tid; idx < 32*256; idx += 256)
        Ash[idx>>8][idx&255] = g_raw[((size_t)jb*SEQ + s0 + (idx>>8))*SEQ + (idx&255)];
    for (int t = tid; t < 64*KSZ; t += 256)
        s_ck[t] = convk[j*64*KSZ + t];
    __syncthreads();

    {   // softmax: 8 lanes per row, 32 cols each
        int rw = tid >> 3, c8 = tid & 7;
        float vloc[32];
        float m = -1e30f;
        #pragma unroll
        for (int k = 0; k < 32; k++) {
            vloc[k] = Ash[rw][c8*32 + k] * inv;
            m = fmaxf(m, vloc[k]);
        }
        for (int off = 4; off; off >>= 1) m = fmaxf(m, __shfl_xor_sync(0xffffffffu, m, off));
        float sum = 0.f;
        #pragma unroll
        for (int k = 0; k < 32; k++) { vloc[k] = expf(vloc[k] - m); sum += vloc[k]; }
        for (int off = 4; off; off >>= 1) sum += __shfl_xor_sync(0xffffffffu, sum, off);
        float sc = fabsf(betas[j]) / sum;
        float al = fabsf(alphas[j]);
        #pragma unroll
        for (int k = 0; k < 32; k++) {
            int t = c8*32 + k;
            float vv = vloc[k] * sc;
            if (t == s0 + rw) vv += al;
            Ash[rw][t] = vv;
        }
    }
    __syncthreads();

    int f = tid & 63, rg = tid >> 6;     // rg: 4 groups of 8 rows
    const float* XP = out + OFF_PROJ + (size_t)bj * SEQ * FEAT;
    float acc[8];
    #pragma unroll
    for (int r = 0; r < 8; r++) acc[r] = 0.f;
    for (int t0 = 0; t0 < 256; t0 += 4) {
        float xp0 = XP[(t0+0)*64 + f];
        float xp1 = XP[(t0+1)*64 + f];
        float xp2 = XP[(t0+2)*64 + f];
        float xp3 = XP[(t0+3)*64 + f];
        #pragma unroll
        for (int r = 0; r < 8; r++) {
            float4 av = *(const float4*)&Ash[rg*8 + r][t0];
            acc[r] = fmaf(av.x, xp0, fmaf(av.y, xp1, fmaf(av.z, xp2, fmaf(av.w, xp3, acc[r]))));
        }
    }

    float th = fabsf(thetas[j]);
    float ga = gammas[j];
    #pragma unroll
    for (int r = 0; r < 8; r++) {
        int s = s0 + rg*8 + r;
        float w3 = 0.f;
        #pragma unroll
        for (int k = 0; k < KSZ; k++) {
            int tt = s + k - 7;
            if (tt >= 0 && tt < SEQ)
                w3 = fmaf(XP[tt*64 + f], s_ck[f*KSZ + k], w3);
        }
        float v = acc[r] + th*w3 + ga * g_comb[((size_t)bj*SEQ + s)*64 + f];
        out[((size_t)bj*SEQ + s)*64 + f] = v;
    }
}

// ---------------- launch ----------------
extern "C" void kernel_launch(void* const* d_in, const int* in_sizes, int n_in,
                              void* d_out, int out_size) {
    const float* x_in   = (const float*)d_in[0];
    const float* proj   = (const float*)d_in[1];
    const float* sw     = (const float*)d_in[3];
    const float* tau    = (const float*)d_in[4];
    const float* temp   = (const float*)d_in[5];
    const float* omiga  = (const float*)d_in[6];
    const float* W2s    = (const float*)d_in[7];
    const float* bs     = (const float*)d_in[8];
    const float* ln_w   = (const float*)d_in[9];
    const float* ln_b   = (const float*)d_in[10];
    const float* alphas = (const float*)d_in[11];
    const float* betas  = (const float*)d_in[12];
    const float* thetas = (const float*)d_in[13];
    const float* gammas = (const float*)d_in[14];
    const float* convk  = (const float*)d_in[15];
    float* out = (float*)d_out;

    cudaFuncSetAttribute(k_raw_tc, cudaFuncAttributeMaxDynamicSharedMemorySize, RAW_SMEM);

    k_statsE <<<Bb*IN_N + 1, 256>>>(x_in, sw, omiga);
    k_kq     <<<Bb*SEQ, 256>>>(proj, tau, temp);
    k_comb   <<<Bb*64, 256>>>(x_in, omiga, tau, temp, ln_w, ln_b);
    k_raw_tc <<<OUT_N*Bb*4, 256, RAW_SMEM>>>();       // captured launch (index 3)
    k_proj   <<<OUT_N*16, 256>>>(out, W2s, bs);
    k_spatial<<<OUT_N*Bb*8, 256>>>(out, convk, temp, alphas, betas, thetas, gammas);
}